// round 4
// baseline (speedup 1.0000x reference)
#include <cuda_runtime.h>
#include <math.h>

#define BRAYS 4096
#define NSAMP 447
#define N3 (64*64*64)          // 262144
#define M3 (128*128*128)       // 2097152
#define VCH 19
#define STEPV 0.015625f        // STEP * VOXEL

typedef unsigned long long u64;
typedef unsigned int u32;

__device__ __forceinline__ void fma2(u64& d, u64 a, u64 b) {
    asm("fma.rn.f32x2 %0, %1, %2, %0;" : "+l"(d) : "l"(a), "l"(b));
}
__device__ __forceinline__ u64 pack2(float lo, float hi) {
    u64 r;
    asm("mov.b64 %0, {%1, %2};" : "=l"(r) : "f"(lo), "f"(hi));
    return r;
}
__device__ __forceinline__ float2 unpack2(u64 v) {
    float2 r;
    asm("mov.b64 {%0, %1}, %2;" : "=f"(r.x), "=f"(r.y) : "l"(v));
    return r;
}
__device__ __forceinline__ u32 tf32of(float x) {
    u32 r;
    asm("cvt.rna.tf32.f32 %0, %1;" : "=r"(r) : "f"(x));
    return r;
}
__device__ __forceinline__ void mma8(float* c, const u32* a, u32 b0, u32 b1) {
    asm volatile(
        "mma.sync.aligned.m16n8k8.row.col.f32.tf32.tf32.f32 "
        "{%0,%1,%2,%3},{%4,%5,%6,%7},{%8,%9},{%0,%1,%2,%3};"
        : "+f"(c[0]), "+f"(c[1]), "+f"(c[2]), "+f"(c[3])
        : "r"(a[0]), "r"(a[1]), "r"(a[2]), "r"(a[3]), "r"(b0), "r"(b1));
}

// ---------------- scratch (device globals; no runtime allocation) -----------
__device__ float g_x1[64 * N3];
__device__ float g_x2[64 * N3];
__device__ float g_vols[VCH * M3];
__device__ float g_sdfs[BRAYS * NSAMP];
__device__ float g_rgbs[BRAYS * NSAMP * 3];

__global__ void noop_kernel() {}

// ======== tensor-core 3x3x3 conv + BN + ReLU (tf32 3-pass = fp32 acc) =======
// Tile: 8x * 8y * 8z = 512 voxels, 64 out channels. 512 threads = 16 warps.
// Warp w: co-half coh=(w&1)*32 (2 m16 groups), voxel-eighth (w>>1)*64 (8 n8 tiles).
// K loop: chunks of 8 input channels x 27 taps, k=8 per mma.
// Precision: A,B split hi/lo in tf32; acc = AhBh + AhBl + AlBh (fp32-equivalent).
#define CIST 2408            // per-ci smem stride (floats); 2408%32==8 -> conflict-free
#define CONV_SMEM ((8*CIST + 27*64*16) * 4)
template<int CIN, int NCHUNK, int LAYER>
__global__ void __launch_bounds__(512) conv_tc_kernel(
    const float* __restrict__ src0,
    const float* __restrict__ w,
    const float* __restrict__ cb,
    const float* __restrict__ bg, const float* __restrict__ bb,
    const float* __restrict__ bm, const float* __restrict__ bv)
{
    extern __shared__ float smem[];
    float* s_in = smem;                      // [ci8][hi/lo 1200][z10][y10][x12]
    float* s_w  = smem + 8 * CIST;           // [tap27][co64][hi8|lo8 ci]
    __shared__ float s_a[64], s_c[64];
    float* dst = (LAYER == 1) ? g_x1 : g_x2;

    const int tid = threadIdx.x;
    const int x0 = blockIdx.x * 8, y0 = blockIdx.y * 8, z0 = blockIdx.z * 8;
    if (tid < 64) {
        float s = bg[tid] * rsqrtf(bv[tid] + 1e-5f);
        s_a[tid] = s;
        s_c[tid] = cb[tid] * s + bb[tid] - bm[tid] * s;
    }
    const int warp = tid >> 5, lane = tid & 31;
    const int g = lane >> 2, tg = lane & 3;
    const int coh = (warp & 1) * 32;
    const int q8  = (warp >> 1) * 8;          // first n-tile of this warp's eighth

    float acc[2][8][4];
#pragma unroll
    for (int m = 0; m < 2; m++)
#pragma unroll
        for (int j = 0; j < 8; j++)
#pragma unroll
            for (int c = 0; c < 4; c++) acc[m][j][c] = 0.f;

    const u32* s_in_u = (const u32*)s_in;
    const u32* s_w_u  = (const u32*)s_w;

    for (int ch = 0; ch < NCHUNK; ch++) {
        __syncthreads();
        // stage input tile, split hi/lo tf32
        for (int i = tid; i < 8 * 1200; i += 512) {
            int cil = i / 1200, rem = i - cil * 1200;
            int z = rem / 120, y = (rem / 12) % 10, x = rem % 12;
            float v = 0.f;
            int gx = x0 - 1 + x, gy = y0 - 1 + y, gz = z0 - 1 + z;
            int ci = ch * 8 + cil;
            if (x < 10 && ci < CIN && (unsigned)gx < 64u && (unsigned)gy < 64u
                && (unsigned)gz < 64u) {
                const float* sp = (ci < 12) ? (src0 + ci * N3) : (g_x1 + (ci - 12) * N3);
                v = __ldg(&sp[(gz * 64 + gy) * 64 + gx]);
            }
            u32 hi = tf32of(v);
            float fh = __uint_as_float(hi);
            u32 lo = tf32of(v - fh);
            int off = cil * CIST + z * 120 + y * 12 + x;
            s_in[off] = __uint_as_float(hi);
            s_in[off + 1200] = __uint_as_float(lo);
        }
        // stage weights, split hi/lo tf32: layout [tap][co][hi ci8 | lo ci8]
        for (int i = tid; i < 27 * 64 * 8; i += 512) {
            int ci = i & 7, co = (i >> 3) & 63, tap = i >> 9;
            int cig = ch * 8 + ci;
            float v = (cig < CIN) ? __ldg(&w[co * (CIN * 27) + cig * 27 + tap]) : 0.f;
            u32 hi = tf32of(v);
            float fh = __uint_as_float(hi);
            u32 lo = tf32of(v - fh);
            int off = (tap * 64 + co) * 16 + ci;
            s_w[off] = __uint_as_float(hi);
            s_w[off + 8] = __uint_as_float(lo);
        }
        __syncthreads();
#pragma unroll 1
        for (int tap = 0; tap < 27; tap++) {
            int kz = tap / 9, ky = (tap / 3) % 3, kx = tap % 3;
            u32 ah[2][4], al[2][4];
#pragma unroll
            for (int mg = 0; mg < 2; mg++) {
                int r0 = (tap * 64 + coh + 16 * mg + g) * 16;
                int r1 = r0 + 8 * 16;
                ah[mg][0] = s_w_u[r0 + tg];
                ah[mg][1] = s_w_u[r1 + tg];
                ah[mg][2] = s_w_u[r0 + tg + 4];
                ah[mg][3] = s_w_u[r1 + tg + 4];
                al[mg][0] = s_w_u[r0 + 8 + tg];
                al[mg][1] = s_w_u[r1 + 8 + tg];
                al[mg][2] = s_w_u[r0 + 8 + tg + 4];
                al[mg][3] = s_w_u[r1 + 8 + tg + 4];
            }
#pragma unroll
            for (int j = 0; j < 8; j++) {
                int nt = q8 + j;
                int y = nt & 7, z = nt >> 3;
                int rowoff = ((z + kz) * 10 + (y + ky)) * 12 + g + kx;
                u32 bh0 = s_in_u[tg * CIST + rowoff];
                u32 bh1 = s_in_u[(tg + 4) * CIST + rowoff];
                u32 bl0 = s_in_u[tg * CIST + 1200 + rowoff];
                u32 bl1 = s_in_u[(tg + 4) * CIST + 1200 + rowoff];
                mma8(acc[0][j], ah[0], bh0, bh1);
                mma8(acc[1][j], ah[1], bh0, bh1);
                mma8(acc[0][j], ah[0], bl0, bl1);
                mma8(acc[1][j], ah[1], bl0, bl1);
                mma8(acc[0][j], al[0], bh0, bh1);
                mma8(acc[1][j], al[1], bh0, bh1);
            }
        }
    }
    // epilogue: BN + ReLU, write g_x1/g_x2
#pragma unroll
    for (int mg = 0; mg < 2; mg++) {
        int co0 = coh + 16 * mg;
        int coA = co0 + g, coB = co0 + g + 8;
        float aA = s_a[coA], cA = s_c[coA];
        float aB = s_a[coB], cB = s_c[coB];
#pragma unroll
        for (int j = 0; j < 8; j++) {
            int nt = q8 + j;
            int y = nt & 7, z = nt >> 3;
            int vb = ((z0 + z) * 64 + (y0 + y)) * 64 + x0 + 2 * tg;
            float* c = acc[mg][j];
            *(float2*)(dst + coA * N3 + vb) =
                make_float2(fmaxf(c[0] * aA + cA, 0.f), fmaxf(c[1] * aA + cA, 0.f));
            *(float2*)(dst + coB * N3 + vb) =
                make_float2(fmaxf(c[2] * aB + cB, 0.f), fmaxf(c[3] * aB + cB, 0.f));
        }
    }
}

// ========= tiled transposed conv: 140 -> 16, k3, stride 2, 64^3 -> 128^3 ====
__global__ void __launch_bounds__(256) deconv_kernel(
    const float* __restrict__ src0,
    const float* __restrict__ w,
    const float* __restrict__ cb)
{
    __shared__ float s_in[4 * 5 * 5 * 10];  // [cil][z5][y5][x10]
    __shared__ float s_w[4 * 27 * 16];      // [cil][kz][ky][kx][co16], flipped

    const int tid = threadIdx.x;
    const int x0 = blockIdx.x * 16, y0 = blockIdx.y * 8, z0 = blockIdx.z * 8;
    const int qx = tid & 3, ty = (tid >> 2) & 7, tz = tid >> 5;
    const int oy = y0 + ty, oz = z0 + tz;

    int nzl, kzv[2], izv[2];
    if ((tz & 1) == 0) { nzl = 1; kzv[0] = 1; izv[0] = tz >> 1; kzv[1] = 1; izv[1] = tz >> 1; }
    else { nzl = 2; kzv[0] = 0; izv[0] = (tz - 1) >> 1; kzv[1] = 2; izv[1] = (tz + 1) >> 1; }
    int nyl, kyv[2], iyv[2];
    if ((ty & 1) == 0) { nyl = 1; kyv[0] = 1; iyv[0] = ty >> 1; kyv[1] = 1; iyv[1] = ty >> 1; }
    else { nyl = 2; kyv[0] = 0; iyv[0] = (ty - 1) >> 1; kyv[1] = 2; iyv[1] = (ty + 1) >> 1; }

    u64 acc2[4][8];
#pragma unroll
    for (int j = 0; j < 4; j++)
#pragma unroll
        for (int c = 0; c < 8; c++) acc2[j][c] = 0ull;

    const int bx2 = x0 >> 1, by2 = y0 >> 1, bz2 = z0 >> 1;

    for (int ch = 0; ch < 35; ch++) {
        __syncthreads();
        for (int i = tid; i < 4 * 250; i += 256) {
            int cil = i / 250, rem = i % 250;
            int z = rem / 50, y2 = (rem / 10) % 5, x = rem % 10;
            float vv = 0.f;
            int gx = bx2 + x, gy = by2 + y2, gz = bz2 + z;
            if (gx < 64 && gy < 64 && gz < 64) {
                int ci = ch * 4 + cil;
                const float* sp = (ci < 12) ? (src0 + ci * N3)
                                : (ci < 76) ? (g_x1 + (ci - 12) * N3)
                                            : (g_x2 + (ci - 76) * N3);
                vv = __ldg(&sp[(gz * 64 + gy) * 64 + gx]);
            }
            s_in[i] = vv;
        }
        for (int i = tid; i < 4 * 27 * 16; i += 256) {
            int co = i & 15, rest = i >> 4;
            int k = rest % 27, cil = rest / 27;
            int kz_ = k / 9, ky_ = (k / 3) % 3, kx_ = k % 3;
            s_w[i] = __ldg(&w[(ch * 4 + cil) * (16 * 27) + co * 27
                              + (2 - kz_) * 9 + (2 - ky_) * 3 + (2 - kx_)]);
        }
        __syncthreads();
#pragma unroll
        for (int cil = 0; cil < 4; cil++) {
            for (int a = 0; a < nzl; a++) {
                int kz = kzv[a], iz = izv[a];
                for (int b = 0; b < nyl; b++) {
                    int ky = kyv[b], iy = iyv[b];
                    const float* rowp = s_in + ((cil * 5 + iz) * 5 + iy) * 10 + 2 * qx;
                    float2 rA = *(const float2*)rowp;
                    float  r2v = rowp[2];
                    u64 r0p = pack2(rA.x, rA.x);
                    u64 r1p = pack2(rA.y, rA.y);
                    u64 r2p = pack2(r2v, r2v);
                    const float* wb = s_w + ((cil * 27) + kz * 9 + ky * 3) * 16;
                    const u64* q0 = (const u64*)wb;
                    const u64* q1 = (const u64*)(wb + 16);
                    const u64* q2 = (const u64*)(wb + 32);
#pragma unroll
                    for (int c = 0; c < 8; c++) {
                        u64 w0p = q0[c], w1p = q1[c], w2p = q2[c];
                        fma2(acc2[0][c], r0p, w1p);
                        fma2(acc2[1][c], r0p, w0p);
                        fma2(acc2[1][c], r1p, w2p);
                        fma2(acc2[2][c], r1p, w1p);
                        fma2(acc2[3][c], r1p, w0p);
                        fma2(acc2[3][c], r2p, w2p);
                    }
                }
            }
        }
    }
    int obase = (oz * 128 + oy) * 128 + x0 + 4 * qx;
#pragma unroll
    for (int c = 0; c < 8; c++) {
        float2 p0 = unpack2(acc2[0][c]);
        float2 p1 = unpack2(acc2[1][c]);
        float2 p2 = unpack2(acc2[2][c]);
        float2 p3 = unpack2(acc2[3][c]);
        int co0 = 2 * c;
        float b0v = __ldg(&cb[co0]), b1v = __ldg(&cb[co0 + 1]);
        *(float4*)(g_vols + co0 * M3 + obase) =
            make_float4(p0.x + b0v, p1.x + b0v, p2.x + b0v, p3.x + b0v);
        *(float4*)(g_vols + (co0 + 1) * M3 + obase) =
            make_float4(p0.y + b1v, p1.y + b1v, p2.y + b1v, p3.y + b1v);
    }
}

// ---------------- sobel: density -> 3 gradient channels, 5x5x5 pad2 ---------
__global__ void sobel_kernel(const float* __restrict__ sob)
{
    __shared__ float ks[3 * 125];
    const int tid = threadIdx.x;
    for (int i = tid; i < 375; i += 256) ks[i] = sob[i];
    __syncthreads();
    int v = blockIdx.x * 256 + tid;
    if (v >= M3) return;
    int x = v & 127, y = (v >> 7) & 127, z = v >> 14;
    float a0 = 0.f, a1 = 0.f, a2 = 0.f;
    for (int kz = 0; kz < 5; kz++) { int zz = z + kz - 2; if ((unsigned)zz >= 128u) continue;
    for (int ky = 0; ky < 5; ky++) { int yy = y + ky - 2; if ((unsigned)yy >= 128u) continue;
    for (int kx = 0; kx < 5; kx++) { int xx = x + kx - 2; if ((unsigned)xx >= 128u) continue;
        float val = g_vols[(zz * 128 + yy) * 128 + xx];
        int k = kz * 25 + ky * 5 + kx;
        a0 += val * ks[k];
        a1 += val * ks[125 + k];
        a2 += val * ks[250 + k];
    }}}
    g_vols[16 * M3 + v] = a0;
    g_vols[17 * M3 + v] = a1;
    g_vols[18 * M3 + v] = a2;
}

// ------------- per-sample: ray AABB, trilinear gather, MLP -------------------
__global__ void __launch_bounds__(128)
sample_kernel(const float* __restrict__ rays_o, const float* __restrict__ rays_d,
              const float* __restrict__ viewdirs,
              const float* __restrict__ w0, const float* __restrict__ b0,
              const float* __restrict__ w1, const float* __restrict__ b1,
              const float* __restrict__ w2, const float* __restrict__ b2,
              const float* __restrict__ w3, const float* __restrict__ b3,
              float* __restrict__ out)
{
    __shared__ float s_w0[58 * 64];
    __shared__ float s_w1[64 * 64];
    __shared__ float s_w2[64 * 64];
    __shared__ float s_w3[64 * 3];
    const int tid = threadIdx.x;
    for (int i = tid; i < 58 * 64; i += 128) s_w0[i] = w0[i];
    for (int i = tid; i < 64 * 64; i += 128) { s_w1[i] = w1[i]; s_w2[i] = w2[i]; }
    for (int i = tid; i < 192; i += 128) s_w3[i] = w3[i];
    __syncthreads();

    int idx = blockIdx.x * 128 + tid;
    if (idx >= BRAYS * NSAMP) return;
    int ray = idx / NSAMP;
    int s   = idx - ray * NSAMP;

    float ox = rays_o[ray * 3 + 0], oy = rays_o[ray * 3 + 1], oz = rays_o[ray * 3 + 2];
    float dx = rays_d[ray * 3 + 0], dy = rays_d[ray * 3 + 1], dz = rays_d[ray * 3 + 2];
    float vx = (dx == 0.f) ? 1e-6f : dx;
    float vy = (dy == 0.f) ? 1e-6f : dy;
    float vz = (dz == 0.f) ? 1e-6f : dz;
    float rax = (1.f - ox) / vx, rbx = (-1.f - ox) / vx;
    float ray_ = (1.f - oy) / vy, rby = (-1.f - oy) / vy;
    float raz = (1.f - oz) / vz, rbz = (-1.f - oz) / vz;
    float tmn = fmaxf(fmaxf(fminf(rax, rbx), fminf(ray_, rby)), fminf(raz, rbz));
    float tmx = fminf(fminf(fmaxf(rax, rbx), fmaxf(ray_, rby)), fmaxf(raz, rbz));
    float t_min = fminf(fmaxf(tmn, 0.05f), 2.5f);
    float t_max = fminf(fmaxf(tmx, 0.05f), 2.5f);
    bool mask = (t_max <= t_min);
    float dn = sqrtf(dx * dx + dy * dy + dz * dz);
    float interpx = t_min + STEPV * (float)s / dn;
    float px = ox + dx * interpx, py = oy + dy * interpx, pz = oz + dz * interpx;
    mask = mask || (px < -1.f) || (px > 1.f) || (py < -1.f) || (py > 1.f)
                || (pz < -1.f) || (pz > 1.f);
    if (mask) {
        g_sdfs[idx] = 100.f;
        g_rgbs[idx * 3 + 0] = 0.f;
        g_rgbs[idx * 3 + 1] = 0.f;
        g_rgbs[idx * 3 + 2] = 0.f;
        if (s == NSAMP - 1) out[BRAYS * 5 + ray] = 0.f;
        return;
    }
    float fx = fminf(fmaxf((px + 1.f) * 63.5f, 0.f), 127.f);
    float fy = fminf(fmaxf((py + 1.f) * 63.5f, 0.f), 127.f);
    float fz = fminf(fmaxf((pz + 1.f) * 63.5f, 0.f), 127.f);
    int i0x = (int)floorf(fx), i0y = (int)floorf(fy), i0z = (int)floorf(fz);
    int i1x = min(i0x + 1, 127), i1y = min(i0y + 1, 127), i1z = min(i0z + 1, 127);
    float twx = fx - (float)i0x, twy = fy - (float)i0y, twz = fz - (float)i0z;
    float wx0 = 1.f - twx, wy0 = 1.f - twy, wz0 = 1.f - twz;
    int o00 = (i0x * 128 + i0y) * 128;
    int o01 = (i0x * 128 + i1y) * 128;
    int o10 = (i1x * 128 + i0y) * 128;
    int o11 = (i1x * 128 + i1y) * 128;
    float w000 = wx0 * wy0 * wz0, w001 = wx0 * wy0 * twz;
    float w010 = wx0 * twy * wz0, w011 = wx0 * twy * twz;
    float w100 = twx * wy0 * wz0, w101 = twx * wy0 * twz;
    float w110 = twx * twy * wz0, w111 = twx * twy * twz;
    float samp[19];
#pragma unroll
    for (int c = 0; c < 19; c++) {
        const float* vc = g_vols + c * M3;
        samp[c] = w000 * __ldg(&vc[o00 + i0z]) + w001 * __ldg(&vc[o00 + i1z])
                + w010 * __ldg(&vc[o01 + i0z]) + w011 * __ldg(&vc[o01 + i1z])
                + w100 * __ldg(&vc[o10 + i0z]) + w101 * __ldg(&vc[o10 + i1z])
                + w110 * __ldg(&vc[o11 + i0z]) + w111 * __ldg(&vc[o11 + i1z]);
    }
    g_sdfs[idx] = samp[0];
    float gx = samp[16], gy = samp[17], gz = samp[18];
    float gn = sqrtf(gx * gx + gy * gy + gz * gz);
    float inv = 1.f / fmaxf(gn, 1e-12f);
    float nxx = gx * inv, nyy = gy * inv, nzz = gz * inv;
    float ux = viewdirs[ray * 3 + 0], uy = viewdirs[ray * 3 + 1], uz = viewdirs[ray * 3 + 2];
    float dot = -(ux * nxx + uy * nyy + uz * nzz);
    if (s == NSAMP - 1) out[BRAYS * 5 + ray] = -dot;
    float rx = 2.f * dot * nxx + ux;
    float ry = 2.f * dot * nyy + uy;
    float rz = 2.f * dot * nzz + uz;

    float h[58];
#pragma unroll
    for (int c = 0; c < 15; c++) h[c] = samp[1 + c];
    h[15] = dot;
    h[16] = rx; h[17] = ry; h[18] = rz;
    {
        int p = 19;
        float fr = 1.f;
#pragma unroll
        for (int e = 0; e < 6; e++) {
            float sx, cx, sy, cy, sz, cz;
            __sincosf(rx * fr, &sx, &cx);
            __sincosf(ry * fr, &sy, &cy);
            __sincosf(rz * fr, &sz, &cz);
            h[p + 0] = sx; h[p + 1] = sy; h[p + 2] = sz;
            h[p + 3] = cx; h[p + 4] = cy; h[p + 5] = cz;
            p += 6;
            fr *= 2.f;
        }
    }
    h[55] = px; h[56] = py; h[57] = pz;

    u64 acc2[32];
#pragma unroll
    for (int j = 0; j < 32; j++) {
        float2 bb = *(const float2*)(b0 + 2 * j);
        acc2[j] = pack2(bb.x, bb.y);
    }
#pragma unroll 1
    for (int i = 0; i < 58; i++) {
        u64 hv2 = pack2(h[i], h[i]);
        const u64* wp = (const u64*)(s_w0 + i * 64);
#pragma unroll
        for (int j = 0; j < 32; j++) fma2(acc2[j], hv2, wp[j]);
    }
    float act[64];
#pragma unroll
    for (int j = 0; j < 32; j++) {
        float2 p = unpack2(acc2[j]);
        act[2*j] = fmaxf(p.x, 0.f); act[2*j+1] = fmaxf(p.y, 0.f);
        float2 bb = *(const float2*)(b1 + 2 * j);
        acc2[j] = pack2(bb.x, bb.y);
    }
#pragma unroll 1
    for (int i = 0; i < 64; i++) {
        u64 hv2 = pack2(act[i], act[i]);
        const u64* wp = (const u64*)(s_w1 + i * 64);
#pragma unroll
        for (int j = 0; j < 32; j++) fma2(acc2[j], hv2, wp[j]);
    }
#pragma unroll
    for (int j = 0; j < 32; j++) {
        float2 p = unpack2(acc2[j]);
        act[2*j] = fmaxf(p.x, 0.f); act[2*j+1] = fmaxf(p.y, 0.f);
        float2 bb = *(const float2*)(b2 + 2 * j);
        acc2[j] = pack2(bb.x, bb.y);
    }
#pragma unroll 1
    for (int i = 0; i < 64; i++) {
        u64 hv2 = pack2(act[i], act[i]);
        const u64* wp = (const u64*)(s_w2 + i * 64);
#pragma unroll
        for (int j = 0; j < 32; j++) fma2(acc2[j], hv2, wp[j]);
    }
#pragma unroll
    for (int j = 0; j < 32; j++) {
        float2 p = unpack2(acc2[j]);
        act[2*j] = fmaxf(p.x, 0.f); act[2*j+1] = fmaxf(p.y, 0.f);
    }
    float r0 = __ldg(&b3[0]), r1 = __ldg(&b3[1]), r2 = __ldg(&b3[2]);
#pragma unroll 1
    for (int i = 0; i < 64; i++) {
        float hv = act[i];
        r0 += hv * s_w3[i * 3 + 0];
        r1 += hv * s_w3[i * 3 + 1];
        r2 += hv * s_w3[i * 3 + 2];
    }
    g_rgbs[idx * 3 + 0] = r0;
    g_rgbs[idx * 3 + 1] = r1;
    g_rgbs[idx * 3 + 2] = r2;
}

// ---------------- per-ray compositing: warp-per-ray with product scan --------
__global__ void __launch_bounds__(256)
render_kernel(const float* __restrict__ rays_o,
              const float* __restrict__ rays_d,
              const float* __restrict__ variance,
              float* __restrict__ out)
{
    int warp = (blockIdx.x * 256 + threadIdx.x) >> 5;
    int lane = threadIdx.x & 31;
    if (warp >= BRAYS) return;
    int ray = warp;
    float scale = expf(variance[0] * 10.f);
    float ox = rays_o[ray * 3 + 0], oy = rays_o[ray * 3 + 1], oz = rays_o[ray * 3 + 2];
    float dx = rays_d[ray * 3 + 0], dy = rays_d[ray * 3 + 1], dz = rays_d[ray * 3 + 2];
    float vx = (dx == 0.f) ? 1e-6f : dx;
    float vy = (dy == 0.f) ? 1e-6f : dy;
    float vz = (dz == 0.f) ? 1e-6f : dz;
    float rax = (1.f - ox) / vx, rbx = (-1.f - ox) / vx;
    float ray_ = (1.f - oy) / vy, rby = (-1.f - oy) / vy;
    float raz = (1.f - oz) / vz, rbz = (-1.f - oz) / vz;
    float tmn = fmaxf(fmaxf(fminf(rax, rbx), fminf(ray_, rby)), fminf(raz, rbz));
    float t_min = fminf(fmaxf(tmn, 0.05f), 2.5f);
    float dn = sqrtf(dx * dx + dy * dy + dz * dz);
    float base_dist = t_min * dn;

    const float* sd = g_sdfs + ray * NSAMP;
    float T = 1.f, rgb0 = 0.f, rgb1 = 0.f, rgb2 = 0.f, depth = 0.f;

    for (int base = 0; base < NSAMP - 1; base += 32) {
        int s = base + lane;
        bool v = s < NSAMP - 1;
        float alpha = 0.f;
        if (v) {
            float s0 = 1.f / (1.f + expf(-sd[s] * scale));
            float s1 = 1.f / (1.f + expf(-sd[s + 1] * scale));
            alpha = fmaxf((s0 - s1) / (s0 + 1e-10f), 0.f);
        }
        float om = 1.f - alpha;
        float p = om;
#pragma unroll
        for (int off = 1; off < 32; off <<= 1) {
            float t = __shfl_up_sync(0xffffffffu, p, off);
            if (lane >= off) p *= t;
        }
        float excl = __shfl_up_sync(0xffffffffu, p, 1);
        if (lane == 0) excl = 1.f;
        float wgt = T * excl * alpha;
        if (v) {
            out[BRAYS * 6 + ray * (NSAMP - 1) + s] = wgt;
            rgb0 += wgt * g_rgbs[(ray * NSAMP + s) * 3 + 0];
            rgb1 += wgt * g_rgbs[(ray * NSAMP + s) * 3 + 1];
            rgb2 += wgt * g_rgbs[(ray * NSAMP + s) * 3 + 2];
            depth += wgt * (base_dist + STEPV * (float)s);
        }
        T *= __shfl_sync(0xffffffffu, p, 31);
    }
#pragma unroll
    for (int off = 16; off; off >>= 1) {
        rgb0 += __shfl_xor_sync(0xffffffffu, rgb0, off);
        rgb1 += __shfl_xor_sync(0xffffffffu, rgb1, off);
        rgb2 += __shfl_xor_sync(0xffffffffu, rgb2, off);
        depth += __shfl_xor_sync(0xffffffffu, depth, off);
    }
    if (lane == 0) {
        out[ray * 3 + 0] = rgb0;
        out[ray * 3 + 1] = rgb1;
        out[ray * 3 + 2] = rgb2;
        out[BRAYS * 3 + ray] = depth;
        out[BRAYS * 4 + ray] = T;
    }
}

// -----------------------------------------------------------------------------
extern "C" void kernel_launch(void* const* d_in, const int* in_sizes, int n_in,
                              void* d_out, int out_size)
{
    const float* rays_o   = (const float*)d_in[0];
    const float* rays_d   = (const float*)d_in[1];
    const float* viewdirs = (const float*)d_in[2];
    const float* grid     = (const float*)d_in[3];
    const float* c1_w     = (const float*)d_in[4];
    const float* c1_b     = (const float*)d_in[5];
    const float* bn1_g    = (const float*)d_in[6];
    const float* bn1_beta = (const float*)d_in[7];
    const float* bn1_m    = (const float*)d_in[8];
    const float* bn1_v    = (const float*)d_in[9];
    const float* c2_w     = (const float*)d_in[10];
    const float* c2_b     = (const float*)d_in[11];
    const float* bn2_g    = (const float*)d_in[12];
    const float* bn2_beta = (const float*)d_in[13];
    const float* bn2_m    = (const float*)d_in[14];
    const float* bn2_v    = (const float*)d_in[15];
    const float* c3_w     = (const float*)d_in[16];
    const float* c3_b     = (const float*)d_in[17];
    const float* sobel    = (const float*)d_in[18];
    const float* variance = (const float*)d_in[19];
    const float* w0       = (const float*)d_in[20];
    const float* b0       = (const float*)d_in[21];
    const float* w1       = (const float*)d_in[22];
    const float* b1       = (const float*)d_in[23];
    const float* w2       = (const float*)d_in[24];
    const float* b2       = (const float*)d_in[25];
    const float* w3       = (const float*)d_in[26];
    const float* b3       = (const float*)d_in[27];
    float* out = (float*)d_out;

    cudaFuncSetAttribute(conv_tc_kernel<12, 2, 1>,
                         cudaFuncAttributeMaxDynamicSharedMemorySize, CONV_SMEM);
    cudaFuncSetAttribute(conv_tc_kernel<76, 10, 2>,
                         cudaFuncAttributeMaxDynamicSharedMemorySize, CONV_SMEM);

    // two no-op launches shift the ncu capture slot onto the conv2 tensor kernel
    noop_kernel<<<1, 32>>>();
    noop_kernel<<<1, 32>>>();

    dim3 cgrid(8, 8, 8);
    conv_tc_kernel<12, 2, 1><<<cgrid, 512, CONV_SMEM>>>(
        grid, c1_w, c1_b, bn1_g, bn1_beta, bn1_m, bn1_v);
    conv_tc_kernel<76, 10, 2><<<cgrid, 512, CONV_SMEM>>>(
        grid, c2_w, c2_b, bn2_g, bn2_beta, bn2_m, bn2_v);
    deconv_kernel<<<dim3(8, 16, 16), 256>>>(grid, c3_w, c3_b);
    sobel_kernel<<<(M3 + 255) / 256, 256>>>(sobel);
    int total = BRAYS * NSAMP;
    sample_kernel<<<(total + 127) / 128, 128>>>(rays_o, rays_d, viewdirs,
                                                w0, b0, w1, b1, w2, b2, w3, b3, out);
    render_kernel<<<512, 256>>>(rays_o, rays_d, variance, out);
}

// round 5
// speedup vs baseline: 1.0086x; 1.0086x over previous
#include <cuda_runtime.h>
#include <math.h>

#define BRAYS 4096
#define NSAMP 447
#define N3 (64*64*64)          // 262144
#define M3 (128*128*128)       // 2097152
#define VCH 19
#define STEPV 0.015625f        // STEP * VOXEL

typedef unsigned long long u64;
typedef unsigned int u32;

__device__ __forceinline__ void fma2(u64& d, u64 a, u64 b) {
    asm("fma.rn.f32x2 %0, %1, %2, %0;" : "+l"(d) : "l"(a), "l"(b));
}
__device__ __forceinline__ u64 pack2(float lo, float hi) {
    u64 r;
    asm("mov.b64 %0, {%1, %2};" : "=l"(r) : "f"(lo), "f"(hi));
    return r;
}
__device__ __forceinline__ float2 unpack2(u64 v) {
    float2 r;
    asm("mov.b64 {%0, %1}, %2;" : "=f"(r.x), "=f"(r.y) : "l"(v));
    return r;
}
__device__ __forceinline__ u32 tf32of(float x) {
    u32 r;
    asm("cvt.rna.tf32.f32 %0, %1;" : "=r"(r) : "f"(x));
    return r;
}
__device__ __forceinline__ void mma8(float* c, const u32* a, u32 b0, u32 b1) {
    asm volatile(
        "mma.sync.aligned.m16n8k8.row.col.f32.tf32.tf32.f32 "
        "{%0,%1,%2,%3},{%4,%5,%6,%7},{%8,%9},{%0,%1,%2,%3};"
        : "+f"(c[0]), "+f"(c[1]), "+f"(c[2]), "+f"(c[3])
        : "r"(a[0]), "r"(a[1]), "r"(a[2]), "r"(a[3]), "r"(b0), "r"(b1));
}

// ---------------- scratch (device globals; no runtime allocation) -----------
__device__ float g_x1[64 * N3];
__device__ float g_x2[64 * N3];
__device__ float g_vols[VCH * M3];
__device__ float g_sdfs[BRAYS * NSAMP];
__device__ float g_rgbs[BRAYS * NSAMP * 3];

// pre-split tf32 hi/lo weight planes, conflict-free layout
// [chunk][tap 27][plane 2][ci 8][co 72]
#define W_CHUNK 31104          // 27*2*8*72
__device__ u32 g_w1p[2 * W_CHUNK];
__device__ u32 g_w2p[10 * W_CHUNK];

template<int CIN, int NCH, int LAYER>
__global__ void prep_w_kernel(const float* __restrict__ w)
{
    u32* dst = (LAYER == 1) ? g_w1p : g_w2p;
    int i = blockIdx.x * 256 + threadIdx.x;
    if (i >= NCH * W_CHUNK) return;
    int ch = i / W_CHUNK, r = i % W_CHUNK;
    int tap = r / 1152; int r2 = r % 1152;
    int plane = r2 / 576; int r3 = r2 % 576;
    int k = r3 / 72, co = r3 % 72;
    int ci = ch * 8 + k;
    float v = 0.f;
    if (co < 64 && ci < CIN) v = __ldg(&w[co * (CIN * 27) + ci * 27 + tap]);
    u32 hi = tf32of(v);
    dst[i] = plane ? tf32of(v - __uint_as_float(hi)) : hi;
}

// ======== tensor-core 3x3x3 conv + BN + ReLU (tf32 3-pass = fp32 acc) =======
// Tile 8x*8y*8z=512 voxels, 64 co, 512 threads = 16 warps.
// Warp: co-half (warp&1)*32, voxel-eighth (warp>>1)*64.
// s_in  [plane2][ci8][stride 1208]  -> B loads bank ≡ tg*24+g (conflict-free)
// s_w   [tap-local 9][plane2][ci8][co 72] -> A loads bank ≡ tg*8+g (conflict-free)
#define SIN_PLANE (8*1208)
#define SW_GRP 10368           // 9*2*8*72
#define CONV_SMEM ((2*SIN_PLANE + SW_GRP)*4)   // 116 KB
template<int CIN, int NCH, int LAYER>
__global__ void __launch_bounds__(512) conv_tc_kernel(
    const float* __restrict__ src0,
    const float* __restrict__ cb,
    const float* __restrict__ bg, const float* __restrict__ bb,
    const float* __restrict__ bm, const float* __restrict__ bv)
{
    extern __shared__ u32 smem_u[];
    u32* s_in = smem_u;
    u32* s_w  = smem_u + 2 * SIN_PLANE;
    __shared__ float s_a[64], s_c[64];
    float* dst = (LAYER == 1) ? g_x1 : g_x2;
    const u32* wp = (LAYER == 1) ? g_w1p : g_w2p;

    const int tid = threadIdx.x;
    const int x0 = blockIdx.x * 8, y0 = blockIdx.y * 8, z0 = blockIdx.z * 8;
    if (tid < 64) {
        float s = bg[tid] * rsqrtf(bv[tid] + 1e-5f);
        s_a[tid] = s;
        s_c[tid] = cb[tid] * s + bb[tid] - bm[tid] * s;
    }
    const int warp = tid >> 5, lane = tid & 31;
    const int g = lane >> 2, tg = lane & 3;
    const int coh = (warp & 1) * 32;
    const int q8  = (warp >> 1) * 8;

    float acc[2][8][4];
#pragma unroll
    for (int m = 0; m < 2; m++)
#pragma unroll
        for (int j = 0; j < 8; j++)
#pragma unroll
            for (int c = 0; c < 4; c++) acc[m][j][c] = 0.f;

    for (int ch = 0; ch < NCH; ch++) {
        __syncthreads();
        // stage input tile hi/lo
        for (int i = tid; i < 8 * 1200; i += 512) {
            int ci = i / 1200, rem = i - ci * 1200;
            int z = rem / 120, rem2 = rem - z * 120;
            int y = rem2 / 12, x = rem2 - y * 12;
            float v = 0.f;
            int gx = x0 - 1 + x, gy = y0 - 1 + y, gz = z0 - 1 + z;
            int cig = ch * 8 + ci;
            if (x < 10 && cig < CIN && (unsigned)gx < 64u && (unsigned)gy < 64u
                && (unsigned)gz < 64u) {
                const float* sp = (cig < 12) ? (src0 + cig * N3)
                                             : (g_x1 + (cig - 12) * N3);
                v = __ldg(&sp[(gz * 64 + gy) * 64 + gx]);
            }
            u32 hi = tf32of(v);
            u32 lo = tf32of(v - __uint_as_float(hi));
            int off = ci * 1208 + z * 120 + y * 12 + x;
            s_in[off] = hi;
            s_in[SIN_PLANE + off] = lo;
        }
        const u32* wsrc = wp + ch * W_CHUNK;
        for (int grp = 0; grp < 3; grp++) {
            __syncthreads();
            const float4* src4 = (const float4*)(wsrc + grp * SW_GRP);
            float4* dst4 = (float4*)s_w;
            for (int i = tid; i < SW_GRP / 4; i += 512) dst4[i] = src4[i];
            __syncthreads();
#pragma unroll 1
            for (int tl = 0; tl < 9; tl++) {
                int tap = grp * 9 + tl;
                int kz = tap / 9, ky = (tap / 3) % 3, kx = tap % 3;
                const u32* wb = s_w + tl * 1152;
                u32 ah[2][4], al[2][4];
#pragma unroll
                for (int mg = 0; mg < 2; mg++) {
                    int c0g = coh + 16 * mg + g;
                    ah[mg][0] = wb[tg * 72 + c0g];
                    ah[mg][1] = wb[tg * 72 + c0g + 8];
                    ah[mg][2] = wb[(tg + 4) * 72 + c0g];
                    ah[mg][3] = wb[(tg + 4) * 72 + c0g + 8];
                    al[mg][0] = wb[576 + tg * 72 + c0g];
                    al[mg][1] = wb[576 + tg * 72 + c0g + 8];
                    al[mg][2] = wb[576 + (tg + 4) * 72 + c0g];
                    al[mg][3] = wb[576 + (tg + 4) * 72 + c0g + 8];
                }
#pragma unroll
                for (int j = 0; j < 8; j++) {
                    int nt = q8 + j;
                    int yy = nt & 7, zz = nt >> 3;
                    int ro = ((zz + kz) * 10 + yy + ky) * 12 + g + kx;
                    u32 bh0 = s_in[tg * 1208 + ro];
                    u32 bh1 = s_in[(tg + 4) * 1208 + ro];
                    u32 bl0 = s_in[SIN_PLANE + tg * 1208 + ro];
                    u32 bl1 = s_in[SIN_PLANE + (tg + 4) * 1208 + ro];
                    mma8(acc[0][j], ah[0], bh0, bh1);
                    mma8(acc[1][j], ah[1], bh0, bh1);
                    mma8(acc[0][j], ah[0], bl0, bl1);
                    mma8(acc[1][j], ah[1], bl0, bl1);
                    mma8(acc[0][j], al[0], bh0, bh1);
                    mma8(acc[1][j], al[1], bh0, bh1);
                }
            }
        }
    }
    // epilogue: BN + ReLU
#pragma unroll
    for (int mg = 0; mg < 2; mg++) {
        int co0 = coh + 16 * mg;
        int coA = co0 + g, coB = co0 + g + 8;
        float aA = s_a[coA], cA = s_c[coA];
        float aB = s_a[coB], cB = s_c[coB];
#pragma unroll
        for (int j = 0; j < 8; j++) {
            int nt = q8 + j;
            int y = nt & 7, z = nt >> 3;
            int vb = ((z0 + z) * 64 + (y0 + y)) * 64 + x0 + 2 * tg;
            float* c = acc[mg][j];
            *(float2*)(dst + coA * N3 + vb) =
                make_float2(fmaxf(c[0] * aA + cA, 0.f), fmaxf(c[1] * aA + cA, 0.f));
            *(float2*)(dst + coB * N3 + vb) =
                make_float2(fmaxf(c[2] * aB + cB, 0.f), fmaxf(c[3] * aB + cB, 0.f));
        }
    }
}

// ========= tiled transposed conv: 140 -> 16, k3, stride 2, 64^3 -> 128^3 ====
__global__ void __launch_bounds__(256) deconv_kernel(
    const float* __restrict__ src0,
    const float* __restrict__ w,
    const float* __restrict__ cb)
{
    __shared__ float s_in[4 * 5 * 5 * 10];
    __shared__ float s_w[4 * 27 * 16];

    const int tid = threadIdx.x;
    const int x0 = blockIdx.x * 16, y0 = blockIdx.y * 8, z0 = blockIdx.z * 8;
    const int qx = tid & 3, ty = (tid >> 2) & 7, tz = tid >> 5;
    const int oy = y0 + ty, oz = z0 + tz;

    int nzl, kzv[2], izv[2];
    if ((tz & 1) == 0) { nzl = 1; kzv[0] = 1; izv[0] = tz >> 1; kzv[1] = 1; izv[1] = tz >> 1; }
    else { nzl = 2; kzv[0] = 0; izv[0] = (tz - 1) >> 1; kzv[1] = 2; izv[1] = (tz + 1) >> 1; }
    int nyl, kyv[2], iyv[2];
    if ((ty & 1) == 0) { nyl = 1; kyv[0] = 1; iyv[0] = ty >> 1; kyv[1] = 1; iyv[1] = ty >> 1; }
    else { nyl = 2; kyv[0] = 0; iyv[0] = (ty - 1) >> 1; kyv[1] = 2; iyv[1] = (ty + 1) >> 1; }

    u64 acc2[4][8];
#pragma unroll
    for (int j = 0; j < 4; j++)
#pragma unroll
        for (int c = 0; c < 8; c++) acc2[j][c] = 0ull;

    const int bx2 = x0 >> 1, by2 = y0 >> 1, bz2 = z0 >> 1;

    for (int ch = 0; ch < 35; ch++) {
        __syncthreads();
        for (int i = tid; i < 4 * 250; i += 256) {
            int cil = i / 250, rem = i % 250;
            int z = rem / 50, y2 = (rem / 10) % 5, x = rem % 10;
            float vv = 0.f;
            int gx = bx2 + x, gy = by2 + y2, gz = bz2 + z;
            if (gx < 64 && gy < 64 && gz < 64) {
                int ci = ch * 4 + cil;
                const float* sp = (ci < 12) ? (src0 + ci * N3)
                                : (ci < 76) ? (g_x1 + (ci - 12) * N3)
                                            : (g_x2 + (ci - 76) * N3);
                vv = __ldg(&sp[(gz * 64 + gy) * 64 + gx]);
            }
            s_in[i] = vv;
        }
        for (int i = tid; i < 4 * 27 * 16; i += 256) {
            int co = i & 15, rest = i >> 4;
            int k = rest % 27, cil = rest / 27;
            int kz_ = k / 9, ky_ = (k / 3) % 3, kx_ = k % 3;
            s_w[i] = __ldg(&w[(ch * 4 + cil) * (16 * 27) + co * 27
                              + (2 - kz_) * 9 + (2 - ky_) * 3 + (2 - kx_)]);
        }
        __syncthreads();
#pragma unroll
        for (int cil = 0; cil < 4; cil++) {
            for (int a = 0; a < nzl; a++) {
                int kz = kzv[a], iz = izv[a];
                for (int b = 0; b < nyl; b++) {
                    int ky = kyv[b], iy = iyv[b];
                    const float* rowp = s_in + ((cil * 5 + iz) * 5 + iy) * 10 + 2 * qx;
                    float2 rA = *(const float2*)rowp;
                    float  r2v = rowp[2];
                    u64 r0p = pack2(rA.x, rA.x);
                    u64 r1p = pack2(rA.y, rA.y);
                    u64 r2p = pack2(r2v, r2v);
                    const float* wb = s_w + ((cil * 27) + kz * 9 + ky * 3) * 16;
                    const u64* q0 = (const u64*)wb;
                    const u64* q1 = (const u64*)(wb + 16);
                    const u64* q2 = (const u64*)(wb + 32);
#pragma unroll
                    for (int c = 0; c < 8; c++) {
                        u64 w0p = q0[c], w1p = q1[c], w2p = q2[c];
                        fma2(acc2[0][c], r0p, w1p);
                        fma2(acc2[1][c], r0p, w0p);
                        fma2(acc2[1][c], r1p, w2p);
                        fma2(acc2[2][c], r1p, w1p);
                        fma2(acc2[3][c], r1p, w0p);
                        fma2(acc2[3][c], r2p, w2p);
                    }
                }
            }
        }
    }
    int obase = (oz * 128 + oy) * 128 + x0 + 4 * qx;
#pragma unroll
    for (int c = 0; c < 8; c++) {
        float2 p0 = unpack2(acc2[0][c]);
        float2 p1 = unpack2(acc2[1][c]);
        float2 p2 = unpack2(acc2[2][c]);
        float2 p3 = unpack2(acc2[3][c]);
        int co0 = 2 * c;
        float b0v = __ldg(&cb[co0]), b1v = __ldg(&cb[co0 + 1]);
        *(float4*)(g_vols + co0 * M3 + obase) =
            make_float4(p0.x + b0v, p1.x + b0v, p2.x + b0v, p3.x + b0v);
        *(float4*)(g_vols + (co0 + 1) * M3 + obase) =
            make_float4(p0.y + b1v, p1.y + b1v, p2.y + b1v, p3.y + b1v);
    }
}

// ---------------- sobel: density -> 3 gradient channels, 5x5x5 pad2 ---------
__global__ void sobel_kernel(const float* __restrict__ sob)
{
    __shared__ float ks[3 * 125];
    const int tid = threadIdx.x;
    for (int i = tid; i < 375; i += 256) ks[i] = sob[i];
    __syncthreads();
    int v = blockIdx.x * 256 + tid;
    if (v >= M3) return;
    int x = v & 127, y = (v >> 7) & 127, z = v >> 14;
    float a0 = 0.f, a1 = 0.f, a2 = 0.f;
    for (int kz = 0; kz < 5; kz++) { int zz = z + kz - 2; if ((unsigned)zz >= 128u) continue;
    for (int ky = 0; ky < 5; ky++) { int yy = y + ky - 2; if ((unsigned)yy >= 128u) continue;
    for (int kx = 0; kx < 5; kx++) { int xx = x + kx - 2; if ((unsigned)xx >= 128u) continue;
        float val = g_vols[(zz * 128 + yy) * 128 + xx];
        int k = kz * 25 + ky * 5 + kx;
        a0 += val * ks[k];
        a1 += val * ks[125 + k];
        a2 += val * ks[250 + k];
    }}}
    g_vols[16 * M3 + v] = a0;
    g_vols[17 * M3 + v] = a1;
    g_vols[18 * M3 + v] = a2;
}

// ------------- per-sample: ray AABB, trilinear gather, MLP -------------------
__global__ void __launch_bounds__(128)
sample_kernel(const float* __restrict__ rays_o, const float* __restrict__ rays_d,
              const float* __restrict__ viewdirs,
              const float* __restrict__ w0, const float* __restrict__ b0,
              const float* __restrict__ w1, const float* __restrict__ b1,
              const float* __restrict__ w2, const float* __restrict__ b2,
              const float* __restrict__ w3, const float* __restrict__ b3,
              float* __restrict__ out)
{
    __shared__ float s_w0[58 * 64];
    __shared__ float s_w1[64 * 64];
    __shared__ float s_w2[64 * 64];
    __shared__ float s_w3[64 * 3];
    const int tid = threadIdx.x;
    for (int i = tid; i < 58 * 64; i += 128) s_w0[i] = w0[i];
    for (int i = tid; i < 64 * 64; i += 128) { s_w1[i] = w1[i]; s_w2[i] = w2[i]; }
    for (int i = tid; i < 192; i += 128) s_w3[i] = w3[i];
    __syncthreads();

    int idx = blockIdx.x * 128 + tid;
    if (idx >= BRAYS * NSAMP) return;
    int ray = idx / NSAMP;
    int s   = idx - ray * NSAMP;

    float ox = rays_o[ray * 3 + 0], oy = rays_o[ray * 3 + 1], oz = rays_o[ray * 3 + 2];
    float dx = rays_d[ray * 3 + 0], dy = rays_d[ray * 3 + 1], dz = rays_d[ray * 3 + 2];
    float vx = (dx == 0.f) ? 1e-6f : dx;
    float vy = (dy == 0.f) ? 1e-6f : dy;
    float vz = (dz == 0.f) ? 1e-6f : dz;
    float rax = (1.f - ox) / vx, rbx = (-1.f - ox) / vx;
    float ray_ = (1.f - oy) / vy, rby = (-1.f - oy) / vy;
    float raz = (1.f - oz) / vz, rbz = (-1.f - oz) / vz;
    float tmn = fmaxf(fmaxf(fminf(rax, rbx), fminf(ray_, rby)), fminf(raz, rbz));
    float tmx = fminf(fminf(fmaxf(rax, rbx), fmaxf(ray_, rby)), fmaxf(raz, rbz));
    float t_min = fminf(fmaxf(tmn, 0.05f), 2.5f);
    float t_max = fminf(fmaxf(tmx, 0.05f), 2.5f);
    bool mask = (t_max <= t_min);
    float dn = sqrtf(dx * dx + dy * dy + dz * dz);
    float interpx = t_min + STEPV * (float)s / dn;
    float px = ox + dx * interpx, py = oy + dy * interpx, pz = oz + dz * interpx;
    mask = mask || (px < -1.f) || (px > 1.f) || (py < -1.f) || (py > 1.f)
                || (pz < -1.f) || (pz > 1.f);
    if (mask) {
        g_sdfs[idx] = 100.f;
        g_rgbs[idx * 3 + 0] = 0.f;
        g_rgbs[idx * 3 + 1] = 0.f;
        g_rgbs[idx * 3 + 2] = 0.f;
        if (s == NSAMP - 1) out[BRAYS * 5 + ray] = 0.f;
        return;
    }
    float fx = fminf(fmaxf((px + 1.f) * 63.5f, 0.f), 127.f);
    float fy = fminf(fmaxf((py + 1.f) * 63.5f, 0.f), 127.f);
    float fz = fminf(fmaxf((pz + 1.f) * 63.5f, 0.f), 127.f);
    int i0x = (int)floorf(fx), i0y = (int)floorf(fy), i0z = (int)floorf(fz);
    int i1x = min(i0x + 1, 127), i1y = min(i0y + 1, 127), i1z = min(i0z + 1, 127);
    float twx = fx - (float)i0x, twy = fy - (float)i0y, twz = fz - (float)i0z;
    float wx0 = 1.f - twx, wy0 = 1.f - twy, wz0 = 1.f - twz;
    int o00 = (i0x * 128 + i0y) * 128;
    int o01 = (i0x * 128 + i1y) * 128;
    int o10 = (i1x * 128 + i0y) * 128;
    int o11 = (i1x * 128 + i1y) * 128;
    float w000 = wx0 * wy0 * wz0, w001 = wx0 * wy0 * twz;
    float w010 = wx0 * twy * wz0, w011 = wx0 * twy * twz;
    float w100 = twx * wy0 * wz0, w101 = twx * wy0 * twz;
    float w110 = twx * twy * wz0, w111 = twx * twy * twz;
    float samp[19];
#pragma unroll
    for (int c = 0; c < 19; c++) {
        const float* vc = g_vols + c * M3;
        samp[c] = w000 * __ldg(&vc[o00 + i0z]) + w001 * __ldg(&vc[o00 + i1z])
                + w010 * __ldg(&vc[o01 + i0z]) + w011 * __ldg(&vc[o01 + i1z])
                + w100 * __ldg(&vc[o10 + i0z]) + w101 * __ldg(&vc[o10 + i1z])
                + w110 * __ldg(&vc[o11 + i0z]) + w111 * __ldg(&vc[o11 + i1z]);
    }
    g_sdfs[idx] = samp[0];
    float gx = samp[16], gy = samp[17], gz = samp[18];
    float gn = sqrtf(gx * gx + gy * gy + gz * gz);
    float inv = 1.f / fmaxf(gn, 1e-12f);
    float nxx = gx * inv, nyy = gy * inv, nzz = gz * inv;
    float ux = viewdirs[ray * 3 + 0], uy = viewdirs[ray * 3 + 1], uz = viewdirs[ray * 3 + 2];
    float dot = -(ux * nxx + uy * nyy + uz * nzz);
    if (s == NSAMP - 1) out[BRAYS * 5 + ray] = -dot;
    float rx = 2.f * dot * nxx + ux;
    float ry = 2.f * dot * nyy + uy;
    float rz = 2.f * dot * nzz + uz;

    float h[58];
#pragma unroll
    for (int c = 0; c < 15; c++) h[c] = samp[1 + c];
    h[15] = dot;
    h[16] = rx; h[17] = ry; h[18] = rz;
    {
        int p = 19;
        float fr = 1.f;
#pragma unroll
        for (int e = 0; e < 6; e++) {
            float sx, cx, sy, cy, sz, cz;
            __sincosf(rx * fr, &sx, &cx);
            __sincosf(ry * fr, &sy, &cy);
            __sincosf(rz * fr, &sz, &cz);
            h[p + 0] = sx; h[p + 1] = sy; h[p + 2] = sz;
            h[p + 3] = cx; h[p + 4] = cy; h[p + 5] = cz;
            p += 6;
            fr *= 2.f;
        }
    }
    h[55] = px; h[56] = py; h[57] = pz;

    u64 acc2[32];
#pragma unroll
    for (int j = 0; j < 32; j++) {
        float2 bb = *(const float2*)(b0 + 2 * j);
        acc2[j] = pack2(bb.x, bb.y);
    }
#pragma unroll 1
    for (int i = 0; i < 58; i++) {
        u64 hv2 = pack2(h[i], h[i]);
        const u64* wp = (const u64*)(s_w0 + i * 64);
#pragma unroll
        for (int j = 0; j < 32; j++) fma2(acc2[j], hv2, wp[j]);
    }
    float act[64];
#pragma unroll
    for (int j = 0; j < 32; j++) {
        float2 p = unpack2(acc2[j]);
        act[2*j] = fmaxf(p.x, 0.f); act[2*j+1] = fmaxf(p.y, 0.f);
        float2 bb = *(const float2*)(b1 + 2 * j);
        acc2[j] = pack2(bb.x, bb.y);
    }
#pragma unroll 1
    for (int i = 0; i < 64; i++) {
        u64 hv2 = pack2(act[i], act[i]);
        const u64* wp = (const u64*)(s_w1 + i * 64);
#pragma unroll
        for (int j = 0; j < 32; j++) fma2(acc2[j], hv2, wp[j]);
    }
#pragma unroll
    for (int j = 0; j < 32; j++) {
        float2 p = unpack2(acc2[j]);
        act[2*j] = fmaxf(p.x, 0.f); act[2*j+1] = fmaxf(p.y, 0.f);
        float2 bb = *(const float2*)(b2 + 2 * j);
        acc2[j] = pack2(bb.x, bb.y);
    }
#pragma unroll 1
    for (int i = 0; i < 64; i++) {
        u64 hv2 = pack2(act[i], act[i]);
        const u64* wp = (const u64*)(s_w2 + i * 64);
#pragma unroll
        for (int j = 0; j < 32; j++) fma2(acc2[j], hv2, wp[j]);
    }
#pragma unroll
    for (int j = 0; j < 32; j++) {
        float2 p = unpack2(acc2[j]);
        act[2*j] = fmaxf(p.x, 0.f); act[2*j+1] = fmaxf(p.y, 0.f);
    }
    float r0 = __ldg(&b3[0]), r1 = __ldg(&b3[1]), r2 = __ldg(&b3[2]);
#pragma unroll 1
    for (int i = 0; i < 64; i++) {
        float hv = act[i];
        r0 += hv * s_w3[i * 3 + 0];
        r1 += hv * s_w3[i * 3 + 1];
        r2 += hv * s_w3[i * 3 + 2];
    }
    g_rgbs[idx * 3 + 0] = r0;
    g_rgbs[idx * 3 + 1] = r1;
    g_rgbs[idx * 3 + 2] = r2;
}

// ---------------- per-ray compositing: warp-per-ray with product scan --------
__global__ void __launch_bounds__(256)
render_kernel(const float* __restrict__ rays_o,
              const float* __restrict__ rays_d,
              const float* __restrict__ variance,
              float* __restrict__ out)
{
    int warp = (blockIdx.x * 256 + threadIdx.x) >> 5;
    int lane = threadIdx.x & 31;
    if (warp >= BRAYS) return;
    int ray = warp;
    float scale = expf(variance[0] * 10.f);
    float ox = rays_o[ray * 3 + 0], oy = rays_o[ray * 3 + 1], oz = rays_o[ray * 3 + 2];
    float dx = rays_d[ray * 3 + 0], dy = rays_d[ray * 3 + 1], dz = rays_d[ray * 3 + 2];
    float vx = (dx == 0.f) ? 1e-6f : dx;
    float vy = (dy == 0.f) ? 1e-6f : dy;
    float vz = (dz == 0.f) ? 1e-6f : dz;
    float rax = (1.f - ox) / vx, rbx = (-1.f - ox) / vx;
    float ray_ = (1.f - oy) / vy, rby = (-1.f - oy) / vy;
    float raz = (1.f - oz) / vz, rbz = (-1.f - oz) / vz;
    float tmn = fmaxf(fmaxf(fminf(rax, rbx), fminf(ray_, rby)), fminf(raz, rbz));
    float t_min = fminf(fmaxf(tmn, 0.05f), 2.5f);
    float dn = sqrtf(dx * dx + dy * dy + dz * dz);
    float base_dist = t_min * dn;

    const float* sd = g_sdfs + ray * NSAMP;
    float T = 1.f, rgb0 = 0.f, rgb1 = 0.f, rgb2 = 0.f, depth = 0.f;

    for (int base = 0; base < NSAMP - 1; base += 32) {
        int s = base + lane;
        bool v = s < NSAMP - 1;
        float alpha = 0.f;
        if (v) {
            float s0 = 1.f / (1.f + expf(-sd[s] * scale));
            float s1 = 1.f / (1.f + expf(-sd[s + 1] * scale));
            alpha = fmaxf((s0 - s1) / (s0 + 1e-10f), 0.f);
        }
        float om = 1.f - alpha;
        float p = om;
#pragma unroll
        for (int off = 1; off < 32; off <<= 1) {
            float t = __shfl_up_sync(0xffffffffu, p, off);
            if (lane >= off) p *= t;
        }
        float excl = __shfl_up_sync(0xffffffffu, p, 1);
        if (lane == 0) excl = 1.f;
        float wgt = T * excl * alpha;
        if (v) {
            out[BRAYS * 6 + ray * (NSAMP - 1) + s] = wgt;
            rgb0 += wgt * g_rgbs[(ray * NSAMP + s) * 3 + 0];
            rgb1 += wgt * g_rgbs[(ray * NSAMP + s) * 3 + 1];
            rgb2 += wgt * g_rgbs[(ray * NSAMP + s) * 3 + 2];
            depth += wgt * (base_dist + STEPV * (float)s);
        }
        T *= __shfl_sync(0xffffffffu, p, 31);
    }
#pragma unroll
    for (int off = 16; off; off >>= 1) {
        rgb0 += __shfl_xor_sync(0xffffffffu, rgb0, off);
        rgb1 += __shfl_xor_sync(0xffffffffu, rgb1, off);
        rgb2 += __shfl_xor_sync(0xffffffffu, rgb2, off);
        depth += __shfl_xor_sync(0xffffffffu, depth, off);
    }
    if (lane == 0) {
        out[ray * 3 + 0] = rgb0;
        out[ray * 3 + 1] = rgb1;
        out[ray * 3 + 2] = rgb2;
        out[BRAYS * 3 + ray] = depth;
        out[BRAYS * 4 + ray] = T;
    }
}

// -----------------------------------------------------------------------------
extern "C" void kernel_launch(void* const* d_in, const int* in_sizes, int n_in,
                              void* d_out, int out_size)
{
    const float* rays_o   = (const float*)d_in[0];
    const float* rays_d   = (const float*)d_in[1];
    const float* viewdirs = (const float*)d_in[2];
    const float* grid     = (const float*)d_in[3];
    const float* c1_w     = (const float*)d_in[4];
    const float* c1_b     = (const float*)d_in[5];
    const float* bn1_g    = (const float*)d_in[6];
    const float* bn1_beta = (const float*)d_in[7];
    const float* bn1_m    = (const float*)d_in[8];
    const float* bn1_v    = (const float*)d_in[9];
    const float* c2_w     = (const float*)d_in[10];
    const float* c2_b     = (const float*)d_in[11];
    const float* bn2_g    = (const float*)d_in[12];
    const float* bn2_beta = (const float*)d_in[13];
    const float* bn2_m    = (const float*)d_in[14];
    const float* bn2_v    = (const float*)d_in[15];
    const float* c3_w     = (const float*)d_in[16];
    const float* c3_b     = (const float*)d_in[17];
    const float* sobel    = (const float*)d_in[18];
    const float* variance = (const float*)d_in[19];
    const float* w0       = (const float*)d_in[20];
    const float* b0       = (const float*)d_in[21];
    const float* w1       = (const float*)d_in[22];
    const float* b1       = (const float*)d_in[23];
    const float* w2       = (const float*)d_in[24];
    const float* b2       = (const float*)d_in[25];
    const float* w3       = (const float*)d_in[26];
    const float* b3       = (const float*)d_in[27];
    float* out = (float*)d_out;

    cudaFuncSetAttribute(conv_tc_kernel<12, 2, 1>,
                         cudaFuncAttributeMaxDynamicSharedMemorySize, CONV_SMEM);
    cudaFuncSetAttribute(conv_tc_kernel<76, 10, 2>,
                         cudaFuncAttributeMaxDynamicSharedMemorySize, CONV_SMEM);

    // launch order keeps ncu slot (#3) on conv2
    prep_w_kernel<12, 2, 1><<<(2 * W_CHUNK + 255) / 256, 256>>>(c1_w);
    prep_w_kernel<76, 10, 2><<<(10 * W_CHUNK + 255) / 256, 256>>>(c2_w);

    dim3 cgrid(8, 8, 8);
    conv_tc_kernel<12, 2, 1><<<cgrid, 512, CONV_SMEM>>>(
        grid, c1_b, bn1_g, bn1_beta, bn1_m, bn1_v);
    conv_tc_kernel<76, 10, 2><<<cgrid, 512, CONV_SMEM>>>(
        grid, c2_b, bn2_g, bn2_beta, bn2_m, bn2_v);
    deconv_kernel<<<dim3(8, 16, 16), 256>>>(grid, c3_w, c3_b);
    sobel_kernel<<<(M3 + 255) / 256, 256>>>(sobel);
    int total = BRAYS * NSAMP;
    sample_kernel<<<(total + 127) / 128, 128>>>(rays_o, rays_d, viewdirs,
                                                w0, b0, w1, b1, w2, b2, w3, b3, out);
    render_kernel<<<512, 256>>>(rays_o, rays_d, variance, out);
}

// round 6
// speedup vs baseline: 1.1460x; 1.1361x over previous
#include <cuda_runtime.h>
#include <cuda_fp16.h>
#include <math.h>

#define BRAYS 4096
#define NSAMP 447
#define N3 (64*64*64)          // 262144
#define M3 (128*128*128)       // 2097152
#define VCH 19
#define STEPV 0.015625f        // STEP * VOXEL

typedef unsigned long long u64;
typedef unsigned int u32;

__device__ __forceinline__ void fma2(u64& d, u64 a, u64 b) {
    asm("fma.rn.f32x2 %0, %1, %2, %0;" : "+l"(d) : "l"(a), "l"(b));
}
__device__ __forceinline__ u64 pack2(float lo, float hi) {
    u64 r;
    asm("mov.b64 %0, {%1, %2};" : "=l"(r) : "f"(lo), "f"(hi));
    return r;
}
__device__ __forceinline__ float2 unpack2(u64 v) {
    float2 r;
    asm("mov.b64 {%0, %1}, %2;" : "=f"(r.x), "=f"(r.y) : "l"(v));
    return r;
}
// m16n8k16 fp16 MMA, fp32 accumulate
__device__ __forceinline__ void mma16(float* c, const u32* a, u32 b0, u32 b1) {
    asm volatile(
        "mma.sync.aligned.m16n8k16.row.col.f32.f16.f16.f32 "
        "{%0,%1,%2,%3},{%4,%5,%6,%7},{%8,%9},{%0,%1,%2,%3};"
        : "+f"(c[0]), "+f"(c[1]), "+f"(c[2]), "+f"(c[3])
        : "r"(a[0]), "r"(a[1]), "r"(a[2]), "r"(a[3]), "r"(b0), "r"(b1));
}
__device__ __forceinline__ u32 packh2(__half a, __half b) {
    __half2 h = __halves2half2(a, b);
    return *(u32*)&h;
}

// ---------------- scratch (device globals; no runtime allocation) -----------
__device__ float g_x1[64 * N3];
__device__ float g_x2[64 * N3];
__device__ float g_vols[VCH * M3];
__device__ float g_sdfs[BRAYS * NSAMP];
__device__ float g_rgbs[BRAYS * NSAMP * 3];

// fp16 hi/lo split weights: [chunk][tap 27][plane 2][cipair 4][co 72] (u32=half2 over ci pair)
#define WCH_H 15552            // 27*2*4*72
__device__ __align__(16) u32 g_w1p[2 * WCH_H];
__device__ __align__(16) u32 g_w2p[10 * WCH_H];

__global__ void prep_w_all(const float* __restrict__ w1,
                           const float* __restrict__ w2)
{
    int i = blockIdx.x * 256 + threadIdx.x;
    const float* w; u32* dst; int CIN; int idx;
    if (i < 2 * WCH_H) { w = w1; dst = g_w1p; CIN = 12; idx = i; }
    else if (i < 12 * WCH_H) { w = w2; dst = g_w2p; CIN = 76; idx = i - 2 * WCH_H; }
    else return;
    int ch = idx / WCH_H, r = idx % WCH_H;
    int tap = r / 576, r2 = r % 576;
    int plane = r2 / 288, r3 = r2 % 288;
    int cp = r3 / 72, co = r3 % 72;
    int ci0 = ch * 8 + 2 * cp;
    float v0 = (co < 64 && ci0 < CIN) ? __ldg(&w[co * (CIN * 27) + ci0 * 27 + tap]) : 0.f;
    float v1 = (co < 64 && ci0 + 1 < CIN) ? __ldg(&w[co * (CIN * 27) + (ci0 + 1) * 27 + tap]) : 0.f;
    __half h0 = __float2half_rn(v0);
    __half l0 = __float2half_rn(v0 - __half2float(h0));
    __half h1 = __float2half_rn(v1);
    __half l1 = __float2half_rn(v1 - __half2float(h1));
    dst[idx] = plane ? packh2(l0, l1) : packh2(h0, h1);
}

// ======== tensor-core 3x3x3 conv + BN + ReLU (fp16 dual-pass = exact) =======
// Tile 8x*8y*8z=512 voxels, 64 co, 512 threads = 16 warps.
// Warp: co-half (warp&1)*32, voxel-eighth (warp>>1)*64.
// s_in  [plane2][cipair4][1208]  (u32=half2 ci even/odd) — banks tg*24+g, clean
// s_w   [tap-local 9][plane2][cipair4][co 72]            — banks tg*8+g, clean
#define SIN_HP (4*1208)        // u32 per plane
#define SW_GRP_H 5184          // 9*2*4*72 u32
#define CONV_SMEM_H ((2*SIN_HP + SW_GRP_H)*4)   // ~58 KB
template<int CIN, int NCH, int LAYER>
__global__ void __launch_bounds__(512) conv_tc_kernel(
    const float* __restrict__ src0,
    const float* __restrict__ cb,
    const float* __restrict__ bg, const float* __restrict__ bb,
    const float* __restrict__ bm, const float* __restrict__ bv)
{
    extern __shared__ u32 smem_u[];
    u32* s_in = smem_u;
    u32* s_w  = smem_u + 2 * SIN_HP;
    __shared__ float s_a[64], s_c[64];
    float* dst = (LAYER == 1) ? g_x1 : g_x2;
    const u32* wp = (LAYER == 1) ? g_w1p : g_w2p;

    const int tid = threadIdx.x;
    const int x0 = blockIdx.x * 8, y0 = blockIdx.y * 8, z0 = blockIdx.z * 8;
    if (tid < 64) {
        float s = bg[tid] * rsqrtf(bv[tid] + 1e-5f);
        s_a[tid] = s;
        s_c[tid] = cb[tid] * s + bb[tid] - bm[tid] * s;
    }
    const int warp = tid >> 5, lane = tid & 31;
    const int g = lane >> 2, tg = lane & 3;
    const int coh = (warp & 1) * 32;
    const int q8  = (warp >> 1) * 8;

    float acc[2][8][4];
#pragma unroll
    for (int m = 0; m < 2; m++)
#pragma unroll
        for (int j = 0; j < 8; j++)
#pragma unroll
            for (int c = 0; c < 4; c++) acc[m][j][c] = 0.f;

    for (int ch = 0; ch < NCH; ch++) {
        __syncthreads();
        // stage input tile: hi/lo fp16, half2 over ci pairs
        for (int i = tid; i < 4 * 1200; i += 512) {
            int cp = i / 1200, rem = i - cp * 1200;
            int z = rem / 120, rem2 = rem - z * 120;
            int y = rem2 / 12, x = rem2 - y * 12;
            int gx = x0 - 1 + x, gy = y0 - 1 + y, gz = z0 - 1 + z;
            bool sp_ok = (x < 10) && (unsigned)gx < 64u && (unsigned)gy < 64u
                         && (unsigned)gz < 64u;
            int ci0 = ch * 8 + 2 * cp;
            float v0 = 0.f, v1 = 0.f;
            if (sp_ok) {
                int gi = (gz * 64 + gy) * 64 + gx;
                if (ci0 < CIN) {
                    const float* sp = (ci0 < 12) ? (src0 + ci0 * N3)
                                                 : (g_x1 + (ci0 - 12) * N3);
                    v0 = __ldg(&sp[gi]);
                }
                if (ci0 + 1 < CIN) {
                    const float* sp = (ci0 + 1 < 12) ? (src0 + (ci0 + 1) * N3)
                                                     : (g_x1 + (ci0 + 1 - 12) * N3);
                    v1 = __ldg(&sp[gi]);
                }
            }
            __half h0 = __float2half_rn(v0);
            __half l0 = __float2half_rn(v0 - __half2float(h0));
            __half h1 = __float2half_rn(v1);
            __half l1 = __float2half_rn(v1 - __half2float(h1));
            int off = cp * 1208 + z * 120 + y * 12 + x;
            s_in[off] = packh2(h0, h1);
            s_in[SIN_HP + off] = packh2(l0, l1);
        }
        const u32* wsrc = wp + ch * WCH_H;
        for (int grp = 0; grp < 3; grp++) {
            __syncthreads();
            const float4* src4 = (const float4*)(wsrc + grp * SW_GRP_H);
            float4* dst4 = (float4*)s_w;
            for (int i = tid; i < SW_GRP_H / 4; i += 512) dst4[i] = src4[i];
            __syncthreads();
#pragma unroll 1
            for (int tl = 0; tl < 9; tl++) {
                int tap = grp * 9 + tl;
                int kz = tap / 9, ky = (tap / 3) % 3, kx = tap % 3;
                const u32* wb = s_w + tl * 576;
                u32 a[2][4];
#pragma unroll
                for (int mg = 0; mg < 2; mg++) {
                    int c0g = coh + 16 * mg + g;
                    a[mg][0] = wb[tg * 72 + c0g];                // hi plane, row g
                    a[mg][1] = wb[tg * 72 + c0g + 8];            // hi plane, row g+8
                    a[mg][2] = wb[(4 + tg) * 72 + c0g];          // lo plane, row g
                    a[mg][3] = wb[(4 + tg) * 72 + c0g + 8];      // lo plane, row g+8
                }
#pragma unroll
                for (int j = 0; j < 8; j++) {
                    int nt = q8 + j;
                    int yy = nt & 7, zz = nt >> 3;
                    int ro = ((zz + kz) * 10 + yy + ky) * 12 + g + kx;
                    u32 b0 = s_in[tg * 1208 + ro];               // hi
                    u32 b1 = s_in[SIN_HP + tg * 1208 + ro];      // lo
                    mma16(acc[0][j], a[0], b0, b1);              // AhBh + AlBl
                    mma16(acc[1][j], a[1], b0, b1);
                    mma16(acc[0][j], a[0], b1, b0);              // AhBl + AlBh
                    mma16(acc[1][j], a[1], b1, b0);
                }
            }
        }
    }
    // epilogue: BN + ReLU
#pragma unroll
    for (int mg = 0; mg < 2; mg++) {
        int co0 = coh + 16 * mg;
        int coA = co0 + g, coB = co0 + g + 8;
        float aA = s_a[coA], cA = s_c[coA];
        float aB = s_a[coB], cB = s_c[coB];
#pragma unroll
        for (int j = 0; j < 8; j++) {
            int nt = q8 + j;
            int y = nt & 7, z = nt >> 3;
            int vb = ((z0 + z) * 64 + (y0 + y)) * 64 + x0 + 2 * tg;
            float* c = acc[mg][j];
            *(float2*)(dst + coA * N3 + vb) =
                make_float2(fmaxf(c[0] * aA + cA, 0.f), fmaxf(c[1] * aA + cA, 0.f));
            *(float2*)(dst + coB * N3 + vb) =
                make_float2(fmaxf(c[2] * aB + cB, 0.f), fmaxf(c[3] * aB + cB, 0.f));
        }
    }
}

// ========= tiled transposed conv: 140 -> 16, k3, stride 2, 64^3 -> 128^3 ====
__global__ void __launch_bounds__(256) deconv_kernel(
    const float* __restrict__ src0,
    const float* __restrict__ w,
    const float* __restrict__ cb)
{
    __shared__ float s_in[4 * 5 * 5 * 10];
    __shared__ float s_w[4 * 27 * 16];

    const int tid = threadIdx.x;
    const int x0 = blockIdx.x * 16, y0 = blockIdx.y * 8, z0 = blockIdx.z * 8;
    const int qx = tid & 3, ty = (tid >> 2) & 7, tz = tid >> 5;
    const int oy = y0 + ty, oz = z0 + tz;

    int nzl, kzv[2], izv[2];
    if ((tz & 1) == 0) { nzl = 1; kzv[0] = 1; izv[0] = tz >> 1; kzv[1] = 1; izv[1] = tz >> 1; }
    else { nzl = 2; kzv[0] = 0; izv[0] = (tz - 1) >> 1; kzv[1] = 2; izv[1] = (tz + 1) >> 1; }
    int nyl, kyv[2], iyv[2];
    if ((ty & 1) == 0) { nyl = 1; kyv[0] = 1; iyv[0] = ty >> 1; kyv[1] = 1; iyv[1] = ty >> 1; }
    else { nyl = 2; kyv[0] = 0; iyv[0] = (ty - 1) >> 1; kyv[1] = 2; iyv[1] = (ty + 1) >> 1; }

    u64 acc2[4][8];
#pragma unroll
    for (int j = 0; j < 4; j++)
#pragma unroll
        for (int c = 0; c < 8; c++) acc2[j][c] = 0ull;

    const int bx2 = x0 >> 1, by2 = y0 >> 1, bz2 = z0 >> 1;

    for (int ch = 0; ch < 35; ch++) {
        __syncthreads();
        for (int i = tid; i < 4 * 250; i += 256) {
            int cil = i / 250, rem = i % 250;
            int z = rem / 50, y2 = (rem / 10) % 5, x = rem % 10;
            float vv = 0.f;
            int gx = bx2 + x, gy = by2 + y2, gz = bz2 + z;
            if (gx < 64 && gy < 64 && gz < 64) {
                int ci = ch * 4 + cil;
                const float* sp = (ci < 12) ? (src0 + ci * N3)
                                : (ci < 76) ? (g_x1 + (ci - 12) * N3)
                                            : (g_x2 + (ci - 76) * N3);
                vv = __ldg(&sp[(gz * 64 + gy) * 64 + gx]);
            }
            s_in[i] = vv;
        }
        for (int i = tid; i < 4 * 27 * 16; i += 256) {
            int co = i & 15, rest = i >> 4;
            int k = rest % 27, cil = rest / 27;
            int kz_ = k / 9, ky_ = (k / 3) % 3, kx_ = k % 3;
            s_w[i] = __ldg(&w[(ch * 4 + cil) * (16 * 27) + co * 27
                              + (2 - kz_) * 9 + (2 - ky_) * 3 + (2 - kx_)]);
        }
        __syncthreads();
#pragma unroll
        for (int cil = 0; cil < 4; cil++) {
            for (int a = 0; a < nzl; a++) {
                int kz = kzv[a], iz = izv[a];
                for (int b = 0; b < nyl; b++) {
                    int ky = kyv[b], iy = iyv[b];
                    const float* rowp = s_in + ((cil * 5 + iz) * 5 + iy) * 10 + 2 * qx;
                    float2 rA = *(const float2*)rowp;
                    float  r2v = rowp[2];
                    u64 r0p = pack2(rA.x, rA.x);
                    u64 r1p = pack2(rA.y, rA.y);
                    u64 r2p = pack2(r2v, r2v);
                    const float* wb = s_w + ((cil * 27) + kz * 9 + ky * 3) * 16;
                    const u64* q0 = (const u64*)wb;
                    const u64* q1 = (const u64*)(wb + 16);
                    const u64* q2 = (const u64*)(wb + 32);
#pragma unroll
                    for (int c = 0; c < 8; c++) {
                        u64 w0p = q0[c], w1p = q1[c], w2p = q2[c];
                        fma2(acc2[0][c], r0p, w1p);
                        fma2(acc2[1][c], r0p, w0p);
                        fma2(acc2[1][c], r1p, w2p);
                        fma2(acc2[2][c], r1p, w1p);
                        fma2(acc2[3][c], r1p, w0p);
                        fma2(acc2[3][c], r2p, w2p);
                    }
                }
            }
        }
    }
    int obase = (oz * 128 + oy) * 128 + x0 + 4 * qx;
#pragma unroll
    for (int c = 0; c < 8; c++) {
        float2 p0 = unpack2(acc2[0][c]);
        float2 p1 = unpack2(acc2[1][c]);
        float2 p2 = unpack2(acc2[2][c]);
        float2 p3 = unpack2(acc2[3][c]);
        int co0 = 2 * c;
        float b0v = __ldg(&cb[co0]), b1v = __ldg(&cb[co0 + 1]);
        *(float4*)(g_vols + co0 * M3 + obase) =
            make_float4(p0.x + b0v, p1.x + b0v, p2.x + b0v, p3.x + b0v);
        *(float4*)(g_vols + (co0 + 1) * M3 + obase) =
            make_float4(p0.y + b1v, p1.y + b1v, p2.y + b1v, p3.y + b1v);
    }
}

// ---------------- sobel: density -> 3 gradient channels, 5x5x5 pad2 ---------
__global__ void sobel_kernel(const float* __restrict__ sob)
{
    __shared__ float ks[3 * 125];
    const int tid = threadIdx.x;
    for (int i = tid; i < 375; i += 256) ks[i] = sob[i];
    __syncthreads();
    int v = blockIdx.x * 256 + tid;
    if (v >= M3) return;
    int x = v & 127, y = (v >> 7) & 127, z = v >> 14;
    float a0 = 0.f, a1 = 0.f, a2 = 0.f;
    for (int kz = 0; kz < 5; kz++) { int zz = z + kz - 2; if ((unsigned)zz >= 128u) continue;
    for (int ky = 0; ky < 5; ky++) { int yy = y + ky - 2; if ((unsigned)yy >= 128u) continue;
    for (int kx = 0; kx < 5; kx++) { int xx = x + kx - 2; if ((unsigned)xx >= 128u) continue;
        float val = g_vols[(zz * 128 + yy) * 128 + xx];
        int k = kz * 25 + ky * 5 + kx;
        a0 += val * ks[k];
        a1 += val * ks[125 + k];
        a2 += val * ks[250 + k];
    }}}
    g_vols[16 * M3 + v] = a0;
    g_vols[17 * M3 + v] = a1;
    g_vols[18 * M3 + v] = a2;
}

// ------------- per-sample: ray AABB, trilinear gather, MLP -------------------
__global__ void __launch_bounds__(128)
sample_kernel(const float* __restrict__ rays_o, const float* __restrict__ rays_d,
              const float* __restrict__ viewdirs,
              const float* __restrict__ w0, const float* __restrict__ b0,
              const float* __restrict__ w1, const float* __restrict__ b1,
              const float* __restrict__ w2, const float* __restrict__ b2,
              const float* __restrict__ w3, const float* __restrict__ b3,
              float* __restrict__ out)
{
    __shared__ float s_w0[58 * 64];
    __shared__ float s_w1[64 * 64];
    __shared__ float s_w2[64 * 64];
    __shared__ float s_w3[64 * 3];
    const int tid = threadIdx.x;
    for (int i = tid; i < 58 * 64; i += 128) s_w0[i] = w0[i];
    for (int i = tid; i < 64 * 64; i += 128) { s_w1[i] = w1[i]; s_w2[i] = w2[i]; }
    for (int i = tid; i < 192; i += 128) s_w3[i] = w3[i];
    __syncthreads();

    int idx = blockIdx.x * 128 + tid;
    if (idx >= BRAYS * NSAMP) return;
    int ray = idx / NSAMP;
    int s   = idx - ray * NSAMP;

    float ox = rays_o[ray * 3 + 0], oy = rays_o[ray * 3 + 1], oz = rays_o[ray * 3 + 2];
    float dx = rays_d[ray * 3 + 0], dy = rays_d[ray * 3 + 1], dz = rays_d[ray * 3 + 2];
    float vx = (dx == 0.f) ? 1e-6f : dx;
    float vy = (dy == 0.f) ? 1e-6f : dy;
    float vz = (dz == 0.f) ? 1e-6f : dz;
    float rax = (1.f - ox) / vx, rbx = (-1.f - ox) / vx;
    float ray_ = (1.f - oy) / vy, rby = (-1.f - oy) / vy;
    float raz = (1.f - oz) / vz, rbz = (-1.f - oz) / vz;
    float tmn = fmaxf(fmaxf(fminf(rax, rbx), fminf(ray_, rby)), fminf(raz, rbz));
    float tmx = fminf(fminf(fmaxf(rax, rbx), fmaxf(ray_, rby)), fmaxf(raz, rbz));
    float t_min = fminf(fmaxf(tmn, 0.05f), 2.5f);
    float t_max = fminf(fmaxf(tmx, 0.05f), 2.5f);
    bool mask = (t_max <= t_min);
    float dn = sqrtf(dx * dx + dy * dy + dz * dz);
    float interpx = t_min + STEPV * (float)s / dn;
    float px = ox + dx * interpx, py = oy + dy * interpx, pz = oz + dz * interpx;
    mask = mask || (px < -1.f) || (px > 1.f) || (py < -1.f) || (py > 1.f)
                || (pz < -1.f) || (pz > 1.f);
    if (mask) {
        g_sdfs[idx] = 100.f;
        g_rgbs[idx * 3 + 0] = 0.f;
        g_rgbs[idx * 3 + 1] = 0.f;
        g_rgbs[idx * 3 + 2] = 0.f;
        if (s == NSAMP - 1) out[BRAYS * 5 + ray] = 0.f;
        return;
    }
    float fx = fminf(fmaxf((px + 1.f) * 63.5f, 0.f), 127.f);
    float fy = fminf(fmaxf((py + 1.f) * 63.5f, 0.f), 127.f);
    float fz = fminf(fmaxf((pz + 1.f) * 63.5f, 0.f), 127.f);
    int i0x = (int)floorf(fx), i0y = (int)floorf(fy), i0z = (int)floorf(fz);
    int i1x = min(i0x + 1, 127), i1y = min(i0y + 1, 127), i1z = min(i0z + 1, 127);
    float twx = fx - (float)i0x, twy = fy - (float)i0y, twz = fz - (float)i0z;
    float wx0 = 1.f - twx, wy0 = 1.f - twy, wz0 = 1.f - twz;
    int o00 = (i0x * 128 + i0y) * 128;
    int o01 = (i0x * 128 + i1y) * 128;
    int o10 = (i1x * 128 + i0y) * 128;
    int o11 = (i1x * 128 + i1y) * 128;
    float w000 = wx0 * wy0 * wz0, w001 = wx0 * wy0 * twz;
    float w010 = wx0 * twy * wz0, w011 = wx0 * twy * twz;
    float w100 = twx * wy0 * wz0, w101 = twx * wy0 * twz;
    float w110 = twx * twy * wz0, w111 = twx * twy * twz;
    float samp[19];
#pragma unroll
    for (int c = 0; c < 19; c++) {
        const float* vc = g_vols + c * M3;
        samp[c] = w000 * __ldg(&vc[o00 + i0z]) + w001 * __ldg(&vc[o00 + i1z])
                + w010 * __ldg(&vc[o01 + i0z]) + w011 * __ldg(&vc[o01 + i1z])
                + w100 * __ldg(&vc[o10 + i0z]) + w101 * __ldg(&vc[o10 + i1z])
                + w110 * __ldg(&vc[o11 + i0z]) + w111 * __ldg(&vc[o11 + i1z]);
    }
    g_sdfs[idx] = samp[0];
    float gx = samp[16], gy = samp[17], gz = samp[18];
    float gn = sqrtf(gx * gx + gy * gy + gz * gz);
    float inv = 1.f / fmaxf(gn, 1e-12f);
    float nxx = gx * inv, nyy = gy * inv, nzz = gz * inv;
    float ux = viewdirs[ray * 3 + 0], uy = viewdirs[ray * 3 + 1], uz = viewdirs[ray * 3 + 2];
    float dot = -(ux * nxx + uy * nyy + uz * nzz);
    if (s == NSAMP - 1) out[BRAYS * 5 + ray] = -dot;
    float rx = 2.f * dot * nxx + ux;
    float ry = 2.f * dot * nyy + uy;
    float rz = 2.f * dot * nzz + uz;

    float h[58];
#pragma unroll
    for (int c = 0; c < 15; c++) h[c] = samp[1 + c];
    h[15] = dot;
    h[16] = rx; h[17] = ry; h[18] = rz;
    {
        int p = 19;
        float fr = 1.f;
#pragma unroll
        for (int e = 0; e < 6; e++) {
            float sx, cx, sy, cy, sz, cz;
            __sincosf(rx * fr, &sx, &cx);
            __sincosf(ry * fr, &sy, &cy);
            __sincosf(rz * fr, &sz, &cz);
            h[p + 0] = sx; h[p + 1] = sy; h[p + 2] = sz;
            h[p + 3] = cx; h[p + 4] = cy; h[p + 5] = cz;
            p += 6;
            fr *= 2.f;
        }
    }
    h[55] = px; h[56] = py; h[57] = pz;

    u64 acc2[32];
#pragma unroll
    for (int j = 0; j < 32; j++) {
        float2 bb = *(const float2*)(b0 + 2 * j);
        acc2[j] = pack2(bb.x, bb.y);
    }
#pragma unroll 1
    for (int i = 0; i < 58; i++) {
        u64 hv2 = pack2(h[i], h[i]);
        const u64* wp = (const u64*)(s_w0 + i * 64);
#pragma unroll
        for (int j = 0; j < 32; j++) fma2(acc2[j], hv2, wp[j]);
    }
    float act[64];
#pragma unroll
    for (int j = 0; j < 32; j++) {
        float2 p = unpack2(acc2[j]);
        act[2*j] = fmaxf(p.x, 0.f); act[2*j+1] = fmaxf(p.y, 0.f);
        float2 bb = *(const float2*)(b1 + 2 * j);
        acc2[j] = pack2(bb.x, bb.y);
    }
#pragma unroll 1
    for (int i = 0; i < 64; i++) {
        u64 hv2 = pack2(act[i], act[i]);
        const u64* wp = (const u64*)(s_w1 + i * 64);
#pragma unroll
        for (int j = 0; j < 32; j++) fma2(acc2[j], hv2, wp[j]);
    }
#pragma unroll
    for (int j = 0; j < 32; j++) {
        float2 p = unpack2(acc2[j]);
        act[2*j] = fmaxf(p.x, 0.f); act[2*j+1] = fmaxf(p.y, 0.f);
        float2 bb = *(const float2*)(b2 + 2 * j);
        acc2[j] = pack2(bb.x, bb.y);
    }
#pragma unroll 1
    for (int i = 0; i < 64; i++) {
        u64 hv2 = pack2(act[i], act[i]);
        const u64* wp = (const u64*)(s_w2 + i * 64);
#pragma unroll
        for (int j = 0; j < 32; j++) fma2(acc2[j], hv2, wp[j]);
    }
#pragma unroll
    for (int j = 0; j < 32; j++) {
        float2 p = unpack2(acc2[j]);
        act[2*j] = fmaxf(p.x, 0.f); act[2*j+1] = fmaxf(p.y, 0.f);
    }
    float r0 = __ldg(&b3[0]), r1 = __ldg(&b3[1]), r2 = __ldg(&b3[2]);
#pragma unroll 1
    for (int i = 0; i < 64; i++) {
        float hv = act[i];
        r0 += hv * s_w3[i * 3 + 0];
        r1 += hv * s_w3[i * 3 + 1];
        r2 += hv * s_w3[i * 3 + 2];
    }
    g_rgbs[idx * 3 + 0] = r0;
    g_rgbs[idx * 3 + 1] = r1;
    g_rgbs[idx * 3 + 2] = r2;
}

// ---------------- per-ray compositing: warp-per-ray with product scan --------
__global__ void __launch_bounds__(256)
render_kernel(const float* __restrict__ rays_o,
              const float* __restrict__ rays_d,
              const float* __restrict__ variance,
              float* __restrict__ out)
{
    int warp = (blockIdx.x * 256 + threadIdx.x) >> 5;
    int lane = threadIdx.x & 31;
    if (warp >= BRAYS) return;
    int ray = warp;
    float scale = expf(variance[0] * 10.f);
    float ox = rays_o[ray * 3 + 0], oy = rays_o[ray * 3 + 1], oz = rays_o[ray * 3 + 2];
    float dx = rays_d[ray * 3 + 0], dy = rays_d[ray * 3 + 1], dz = rays_d[ray * 3 + 2];
    float vx = (dx == 0.f) ? 1e-6f : dx;
    float vy = (dy == 0.f) ? 1e-6f : dy;
    float vz = (dz == 0.f) ? 1e-6f : dz;
    float rax = (1.f - ox) / vx, rbx = (-1.f - ox) / vx;
    float ray_ = (1.f - oy) / vy, rby = (-1.f - oy) / vy;
    float raz = (1.f - oz) / vz, rbz = (-1.f - oz) / vz;
    float tmn = fmaxf(fmaxf(fminf(rax, rbx), fminf(ray_, rby)), fminf(raz, rbz));
    float t_min = fminf(fmaxf(tmn, 0.05f), 2.5f);
    float dn = sqrtf(dx * dx + dy * dy + dz * dz);
    float base_dist = t_min * dn;

    const float* sd = g_sdfs + ray * NSAMP;
    float T = 1.f, rgb0 = 0.f, rgb1 = 0.f, rgb2 = 0.f, depth = 0.f;

    for (int base = 0; base < NSAMP - 1; base += 32) {
        int s = base + lane;
        bool v = s < NSAMP - 1;
        float alpha = 0.f;
        if (v) {
            float s0 = 1.f / (1.f + expf(-sd[s] * scale));
            float s1 = 1.f / (1.f + expf(-sd[s + 1] * scale));
            alpha = fmaxf((s0 - s1) / (s0 + 1e-10f), 0.f);
        }
        float om = 1.f - alpha;
        float p = om;
#pragma unroll
        for (int off = 1; off < 32; off <<= 1) {
            float t = __shfl_up_sync(0xffffffffu, p, off);
            if (lane >= off) p *= t;
        }
        float excl = __shfl_up_sync(0xffffffffu, p, 1);
        if (lane == 0) excl = 1.f;
        float wgt = T * excl * alpha;
        if (v) {
            out[BRAYS * 6 + ray * (NSAMP - 1) + s] = wgt;
            rgb0 += wgt * g_rgbs[(ray * NSAMP + s) * 3 + 0];
            rgb1 += wgt * g_rgbs[(ray * NSAMP + s) * 3 + 1];
            rgb2 += wgt * g_rgbs[(ray * NSAMP + s) * 3 + 2];
            depth += wgt * (base_dist + STEPV * (float)s);
        }
        T *= __shfl_sync(0xffffffffu, p, 31);
    }
#pragma unroll
    for (int off = 16; off; off >>= 1) {
        rgb0 += __shfl_xor_sync(0xffffffffu, rgb0, off);
        rgb1 += __shfl_xor_sync(0xffffffffu, rgb1, off);
        rgb2 += __shfl_xor_sync(0xffffffffu, rgb2, off);
        depth += __shfl_xor_sync(0xffffffffu, depth, off);
    }
    if (lane == 0) {
        out[ray * 3 + 0] = rgb0;
        out[ray * 3 + 1] = rgb1;
        out[ray * 3 + 2] = rgb2;
        out[BRAYS * 3 + ray] = depth;
        out[BRAYS * 4 + ray] = T;
    }
}

// -----------------------------------------------------------------------------
extern "C" void kernel_launch(void* const* d_in, const int* in_sizes, int n_in,
                              void* d_out, int out_size)
{
    const float* rays_o   = (const float*)d_in[0];
    const float* rays_d   = (const float*)d_in[1];
    const float* viewdirs = (const float*)d_in[2];
    const float* grid     = (const float*)d_in[3];
    const float* c1_w     = (const float*)d_in[4];
    const float* c1_b     = (const float*)d_in[5];
    const float* bn1_g    = (const float*)d_in[6];
    const float* bn1_beta = (const float*)d_in[7];
    const float* bn1_m    = (const float*)d_in[8];
    const float* bn1_v    = (const float*)d_in[9];
    const float* c2_w     = (const float*)d_in[10];
    const float* c2_b     = (const float*)d_in[11];
    const float* bn2_g    = (const float*)d_in[12];
    const float* bn2_beta = (const float*)d_in[13];
    const float* bn2_m    = (const float*)d_in[14];
    const float* bn2_v    = (const float*)d_in[15];
    const float* c3_w     = (const float*)d_in[16];
    const float* c3_b     = (const float*)d_in[17];
    const float* sobel    = (const float*)d_in[18];
    const float* variance = (const float*)d_in[19];
    const float* w0       = (const float*)d_in[20];
    const float* b0       = (const float*)d_in[21];
    const float* w1       = (const float*)d_in[22];
    const float* b1       = (const float*)d_in[23];
    const float* w2       = (const float*)d_in[24];
    const float* b2       = (const float*)d_in[25];
    const float* w3       = (const float*)d_in[26];
    const float* b3       = (const float*)d_in[27];
    float* out = (float*)d_out;

    cudaFuncSetAttribute(conv_tc_kernel<12, 2, 1>,
                         cudaFuncAttributeMaxDynamicSharedMemorySize, CONV_SMEM_H);
    cudaFuncSetAttribute(conv_tc_kernel<76, 10, 2>,
                         cudaFuncAttributeMaxDynamicSharedMemorySize, CONV_SMEM_H);

    // launch order: prep(1) conv1(2) conv2(3) deconv(4=ncu slot) sobel sample render
    prep_w_all<<<(12 * WCH_H + 255) / 256, 256>>>(c1_w, c2_w);

    dim3 cgrid(8, 8, 8);
    conv_tc_kernel<12, 2, 1><<<cgrid, 512, CONV_SMEM_H>>>(
        grid, c1_b, bn1_g, bn1_beta, bn1_m, bn1_v);
    conv_tc_kernel<76, 10, 2><<<cgrid, 512, CONV_SMEM_H>>>(
        grid, c2_b, bn2_g, bn2_beta, bn2_m, bn2_v);
    deconv_kernel<<<dim3(8, 16, 16), 256>>>(grid, c3_w, c3_b);
    sobel_kernel<<<(M3 + 255) / 256, 256>>>(sobel);
    int total = BRAYS * NSAMP;
    sample_kernel<<<(total + 127) / 128, 128>>>(rays_o, rays_d, viewdirs,
                                                w0, b0, w1, b1, w2, b2, w3, b3, out);
    render_kernel<<<512, 256>>>(rays_o, rays_d, variance, out);
}

// round 7
// speedup vs baseline: 1.1679x; 1.0191x over previous
#include <cuda_runtime.h>
#include <cuda_fp16.h>
#include <math.h>

#define BRAYS 4096
#define NSAMP 447
#define N3 (64*64*64)          // 262144
#define M3 (128*128*128)       // 2097152
#define VCH 19
#define STEPV 0.015625f        // STEP * VOXEL

typedef unsigned long long u64;
typedef unsigned int u32;

__device__ __forceinline__ void fma2(u64& d, u64 a, u64 b) {
    asm("fma.rn.f32x2 %0, %1, %2, %0;" : "+l"(d) : "l"(a), "l"(b));
}
__device__ __forceinline__ u64 pack2(float lo, float hi) {
    u64 r;
    asm("mov.b64 %0, {%1, %2};" : "=l"(r) : "f"(lo), "f"(hi));
    return r;
}
__device__ __forceinline__ float2 unpack2(u64 v) {
    float2 r;
    asm("mov.b64 {%0, %1}, %2;" : "=f"(r.x), "=f"(r.y) : "l"(v));
    return r;
}
// m16n8k16 fp16 MMA, fp32 accumulate
__device__ __forceinline__ void mma16(float* c, const u32* a, u32 b0, u32 b1) {
    asm volatile(
        "mma.sync.aligned.m16n8k16.row.col.f32.f16.f16.f32 "
        "{%0,%1,%2,%3},{%4,%5,%6,%7},{%8,%9},{%0,%1,%2,%3};"
        : "+f"(c[0]), "+f"(c[1]), "+f"(c[2]), "+f"(c[3])
        : "r"(a[0]), "r"(a[1]), "r"(a[2]), "r"(a[3]), "r"(b0), "r"(b1));
}
__device__ __forceinline__ u32 packh2(__half a, __half b) {
    __half2 h = __halves2half2(a, b);
    return *(u32*)&h;
}

// ---------------- scratch (device globals; no runtime allocation) -----------
__device__ float g_x1[64 * N3];
__device__ float g_x2[64 * N3];
__device__ float g_vols[VCH * M3];
__device__ float g_sdfs[BRAYS * NSAMP];
__device__ float g_rgbs[BRAYS * NSAMP * 3];

// fp16 hi/lo split weights (convs): [chunk][tap 27][plane 2][cipair 4][co 72]
#define WCH_H 15552            // 27*2*4*72
__device__ __align__(16) u32 g_w1p[2 * WCH_H];
__device__ __align__(16) u32 g_w2p[10 * WCH_H];
// deconv weights (flipped): [chunk 18][tap 27][plane 2][cipair 4][co 24]
#define W3_TOTAL (18*27*2*4*24)       // 93312
__device__ __align__(16) u32 g_w3p[W3_TOTAL];

__global__ void prep_w_all(const float* __restrict__ w1,
                           const float* __restrict__ w2,
                           const float* __restrict__ w3)
{
    int i = blockIdx.x * 256 + threadIdx.x;
    if (i < 12 * WCH_H) {
        const float* w; u32* dst; int CIN; int idx;
        if (i < 2 * WCH_H) { w = w1; dst = g_w1p; CIN = 12; idx = i; }
        else { w = w2; dst = g_w2p; CIN = 76; idx = i - 2 * WCH_H; }
        int ch = idx / WCH_H, r = idx % WCH_H;
        int tap = r / 576, r2 = r % 576;
        int plane = r2 / 288, r3 = r2 % 288;
        int cp = r3 / 72, co = r3 % 72;
        int ci0 = ch * 8 + 2 * cp;
        float v0 = (co < 64 && ci0 < CIN) ? __ldg(&w[co * (CIN * 27) + ci0 * 27 + tap]) : 0.f;
        float v1 = (co < 64 && ci0 + 1 < CIN) ? __ldg(&w[co * (CIN * 27) + (ci0 + 1) * 27 + tap]) : 0.f;
        __half h0 = __float2half_rn(v0);
        __half l0 = __float2half_rn(v0 - __half2float(h0));
        __half h1 = __float2half_rn(v1);
        __half l1 = __float2half_rn(v1 - __half2float(h1));
        dst[idx] = plane ? packh2(l0, l1) : packh2(h0, h1);
        return;
    }
    int idx = i - 12 * WCH_H;
    if (idx >= W3_TOTAL) return;
    int co = idx % 24; int t = idx / 24;
    int cp = t % 4; t /= 4;
    int plane = t % 2; t /= 2;
    int tap = t % 27; int ch = t / 27;
    int kz = tap / 9, ky = (tap / 3) % 3, kx = tap % 3;
    int ci0 = ch * 8 + 2 * cp;
    // flipped weight: wf[ci][co][kz][ky][kx] = w3[ci][co][2-kz][2-ky][2-kx]
    float v0 = 0.f, v1 = 0.f;
    if (co < 16) {
        int foff = co * 27 + (2 - kz) * 9 + (2 - ky) * 3 + (2 - kx);
        if (ci0 < 140)     v0 = __ldg(&w3[ci0 * (16 * 27) + foff]);
        if (ci0 + 1 < 140) v1 = __ldg(&w3[(ci0 + 1) * (16 * 27) + foff]);
    }
    __half h0 = __float2half_rn(v0);
    __half l0 = __float2half_rn(v0 - __half2float(h0));
    __half h1 = __float2half_rn(v1);
    __half l1 = __float2half_rn(v1 - __half2float(h1));
    g_w3p[idx] = plane ? packh2(l0, l1) : packh2(h0, h1);
}

// ======== tensor-core 3x3x3 conv + BN + ReLU (fp16 dual-pass = exact) =======
#define SIN_HP (4*1208)
#define SW_GRP_H 5184          // 9*2*4*72 u32
#define CONV_SMEM_H ((2*SIN_HP + SW_GRP_H)*4)
template<int CIN, int NCH, int LAYER>
__global__ void __launch_bounds__(512) conv_tc_kernel(
    const float* __restrict__ src0,
    const float* __restrict__ cb,
    const float* __restrict__ bg, const float* __restrict__ bb,
    const float* __restrict__ bm, const float* __restrict__ bv)
{
    extern __shared__ u32 smem_u[];
    u32* s_in = smem_u;
    u32* s_w  = smem_u + 2 * SIN_HP;
    __shared__ float s_a[64], s_c[64];
    float* dst = (LAYER == 1) ? g_x1 : g_x2;
    const u32* wp = (LAYER == 1) ? g_w1p : g_w2p;

    const int tid = threadIdx.x;
    const int x0 = blockIdx.x * 8, y0 = blockIdx.y * 8, z0 = blockIdx.z * 8;
    if (tid < 64) {
        float s = bg[tid] * rsqrtf(bv[tid] + 1e-5f);
        s_a[tid] = s;
        s_c[tid] = cb[tid] * s + bb[tid] - bm[tid] * s;
    }
    const int warp = tid >> 5, lane = tid & 31;
    const int g = lane >> 2, tg = lane & 3;
    const int coh = (warp & 1) * 32;
    const int q8  = (warp >> 1) * 8;

    float acc[2][8][4];
#pragma unroll
    for (int m = 0; m < 2; m++)
#pragma unroll
        for (int j = 0; j < 8; j++)
#pragma unroll
            for (int c = 0; c < 4; c++) acc[m][j][c] = 0.f;

    for (int ch = 0; ch < NCH; ch++) {
        __syncthreads();
        for (int i = tid; i < 4 * 1200; i += 512) {
            int cp = i / 1200, rem = i - cp * 1200;
            int z = rem / 120, rem2 = rem - z * 120;
            int y = rem2 / 12, x = rem2 - y * 12;
            int gx = x0 - 1 + x, gy = y0 - 1 + y, gz = z0 - 1 + z;
            bool sp_ok = (x < 10) && (unsigned)gx < 64u && (unsigned)gy < 64u
                         && (unsigned)gz < 64u;
            int ci0 = ch * 8 + 2 * cp;
            float v0 = 0.f, v1 = 0.f;
            if (sp_ok) {
                int gi = (gz * 64 + gy) * 64 + gx;
                if (ci0 < CIN) {
                    const float* sp = (ci0 < 12) ? (src0 + ci0 * N3)
                                                 : (g_x1 + (ci0 - 12) * N3);
                    v0 = __ldg(&sp[gi]);
                }
                if (ci0 + 1 < CIN) {
                    const float* sp = (ci0 + 1 < 12) ? (src0 + (ci0 + 1) * N3)
                                                     : (g_x1 + (ci0 + 1 - 12) * N3);
                    v1 = __ldg(&sp[gi]);
                }
            }
            __half h0 = __float2half_rn(v0);
            __half l0 = __float2half_rn(v0 - __half2float(h0));
            __half h1 = __float2half_rn(v1);
            __half l1 = __float2half_rn(v1 - __half2float(h1));
            int off = cp * 1208 + z * 120 + y * 12 + x;
            s_in[off] = packh2(h0, h1);
            s_in[SIN_HP + off] = packh2(l0, l1);
        }
        const u32* wsrc = wp + ch * WCH_H;
        for (int grp = 0; grp < 3; grp++) {
            __syncthreads();
            const float4* src4 = (const float4*)(wsrc + grp * SW_GRP_H);
            float4* dst4 = (float4*)s_w;
            for (int i = tid; i < SW_GRP_H / 4; i += 512) dst4[i] = src4[i];
            __syncthreads();
#pragma unroll 1
            for (int tl = 0; tl < 9; tl++) {
                int tap = grp * 9 + tl;
                int kz = tap / 9, ky = (tap / 3) % 3, kx = tap % 3;
                const u32* wb = s_w + tl * 576;
                u32 a[2][4];
#pragma unroll
                for (int mg = 0; mg < 2; mg++) {
                    int c0g = coh + 16 * mg + g;
                    a[mg][0] = wb[tg * 72 + c0g];
                    a[mg][1] = wb[tg * 72 + c0g + 8];
                    a[mg][2] = wb[(4 + tg) * 72 + c0g];
                    a[mg][3] = wb[(4 + tg) * 72 + c0g + 8];
                }
#pragma unroll
                for (int j = 0; j < 8; j++) {
                    int nt = q8 + j;
                    int yy = nt & 7, zz = nt >> 3;
                    int ro = ((zz + kz) * 10 + yy + ky) * 12 + g + kx;
                    u32 b0 = s_in[tg * 1208 + ro];
                    u32 b1 = s_in[SIN_HP + tg * 1208 + ro];
                    mma16(acc[0][j], a[0], b0, b1);
                    mma16(acc[1][j], a[1], b0, b1);
                    mma16(acc[0][j], a[0], b1, b0);
                    mma16(acc[1][j], a[1], b1, b0);
                }
            }
        }
    }
#pragma unroll
    for (int mg = 0; mg < 2; mg++) {
        int co0 = coh + 16 * mg;
        int coA = co0 + g, coB = co0 + g + 8;
        float aA = s_a[coA], cA = s_c[coA];
        float aB = s_a[coB], cB = s_c[coB];
#pragma unroll
        for (int j = 0; j < 8; j++) {
            int nt = q8 + j;
            int y = nt & 7, z = nt >> 3;
            int vb = ((z0 + z) * 64 + (y0 + y)) * 64 + x0 + 2 * tg;
            float* c = acc[mg][j];
            *(float2*)(dst + coA * N3 + vb) =
                make_float2(fmaxf(c[0] * aA + cA, 0.f), fmaxf(c[1] * aA + cA, 0.f));
            *(float2*)(dst + coB * N3 + vb) =
                make_float2(fmaxf(c[2] * aB + cB, 0.f), fmaxf(c[3] * aB + cB, 0.f));
        }
    }
}

// ======== tensor-core transposed conv (parity-class GEMM, fp16 dual-pass) ===
// Class = output parity (px,py,pz). Within a class all voxels share the tap
// set: even dim -> k=1 (1 tap), odd dim -> k=0,2 (2 taps, input offset 0/+1).
// Block: one 8^3 q-tile of one class; 256 thr = 8 warps; warp = 8 n8 tiles.
#define DC_CP 984              // cipair stride (u32); 984%32==24 -> bank-clean
#define DC_PLANE (4*DC_CP)
__global__ void __launch_bounds__(256) deconv_tc_kernel(
    const float* __restrict__ src0, const float* __restrict__ cb)
{
    __shared__ u32 s_in[2 * DC_PLANE];      // 31.5 KB
    __shared__ u32 s_w[8 * 192];            // 6 KB
    __shared__ float s_bias[16];
    const int tid = threadIdx.x;
    const int cls = blockIdx.z & 7;
    const int qx0 = blockIdx.x * 8, qy0 = blockIdx.y * 8, qz0 = (blockIdx.z >> 3) * 8;
    const int px = cls & 1, py = (cls >> 1) & 1, pz = cls >> 2;
    if (tid < 16) s_bias[tid] = __ldg(&cb[tid]);

    const int nx = px + 1, ny = py + 1, nz = pz + 1;
    const int ntap = nx * ny * nz;
    int kidx[8];
    for (int t = 0; t < ntap; t++) {
        int tx = t % nx, r = t / nx;
        int ty = r % ny, tz = r / ny;
        int kx = px ? (tx ? 2 : 0) : 1;
        int ky = py ? (ty ? 2 : 0) : 1;
        int kz = pz ? (tz ? 2 : 0) : 1;
        kidx[t] = kz * 9 + ky * 3 + kx;
    }

    const int warp = tid >> 5, lane = tid & 31;
    const int g = lane >> 2, tg = lane & 3;

    float acc[8][4];
#pragma unroll
    for (int j = 0; j < 8; j++)
#pragma unroll
        for (int c = 0; c < 4; c++) acc[j][c] = 0.f;

    for (int ch = 0; ch < 18; ch++) {
        __syncthreads();
        // stage 8 ci of the 9^3 input region, fp16 hi/lo
        for (int i = tid; i < 4 * 729; i += 256) {
            int cp = i / 729, rem = i - cp * 729;
            int z = rem / 81, rem2 = rem - z * 81;
            int y = rem2 / 9, x = rem2 - y * 9;
            int gx = qx0 + x, gy = qy0 + y, gz = qz0 + z;
            float v0 = 0.f, v1 = 0.f;
            if (gx < 64 && gy < 64 && gz < 64) {
                int gi = (gz * 64 + gy) * 64 + gx;
                int ci0 = ch * 8 + 2 * cp;
                if (ci0 < 140) {
                    const float* sp = (ci0 < 12) ? (src0 + ci0 * N3)
                                    : (ci0 < 76) ? (g_x1 + (ci0 - 12) * N3)
                                                 : (g_x2 + (ci0 - 76) * N3);
                    v0 = __ldg(&sp[gi]);
                }
                int ci1 = ci0 + 1;
                if (ci1 < 140) {
                    const float* sp = (ci1 < 12) ? (src0 + ci1 * N3)
                                    : (ci1 < 76) ? (g_x1 + (ci1 - 12) * N3)
                                                 : (g_x2 + (ci1 - 76) * N3);
                    v1 = __ldg(&sp[gi]);
                }
            }
            __half h0 = __float2half_rn(v0);
            __half l0 = __float2half_rn(v0 - __half2float(h0));
            __half h1 = __float2half_rn(v1);
            __half l1 = __float2half_rn(v1 - __half2float(h1));
            int off = cp * DC_CP + (z * 9 + y) * 12 + x;
            s_in[off] = packh2(h0, h1);
            s_in[DC_PLANE + off] = packh2(l0, l1);
        }
        // stage only this class's taps
        for (int i = tid; i < ntap * 192; i += 256) {
            int t = i / 192, r = i - t * 192;
            s_w[i] = g_w3p[(ch * 27 + kidx[t]) * 192 + r];
        }
        __syncthreads();
        for (int t = 0; t < ntap; t++) {
            int tx = t % nx, r = t / nx;
            int ty = r % ny, tz = r / ny;
            const u32* wb = s_w + t * 192;
            u32 a[4];
            a[0] = wb[tg * 24 + g];
            a[1] = wb[tg * 24 + g + 8];
            a[2] = wb[96 + tg * 24 + g];
            a[3] = wb[96 + tg * 24 + g + 8];
#pragma unroll
            for (int j = 0; j < 8; j++) {
                int nt = warp * 8 + j;
                int yy = nt & 7, zz = nt >> 3;
                int ro = ((zz + tz) * 9 + (yy + ty)) * 12 + g + tx;
                u32 b0 = s_in[tg * DC_CP + ro];
                u32 b1 = s_in[DC_PLANE + tg * DC_CP + ro];
                mma16(acc[j], a, b0, b1);
                mma16(acc[j], a, b1, b0);
            }
        }
    }
    const int coA = g, coB = g + 8;
    const float bA = s_bias[coA], bB = s_bias[coB];
#pragma unroll
    for (int j = 0; j < 8; j++) {
        int nt = warp * 8 + j;
        int yy = nt & 7, zz = nt >> 3;
        int oz = 2 * (qz0 + zz) + pz, oy = 2 * (qy0 + yy) + py;
        int ox = 2 * (qx0 + 2 * tg) + px;
        int base = (oz * 128 + oy) * 128 + ox;
        g_vols[coA * M3 + base]     = acc[j][0] + bA;
        g_vols[coA * M3 + base + 2] = acc[j][1] + bA;
        g_vols[coB * M3 + base]     = acc[j][2] + bB;
        g_vols[coB * M3 + base + 2] = acc[j][3] + bB;
    }
}

// ---------------- sobel: density -> 3 gradient channels, 5x5x5 pad2 ---------
__global__ void sobel_kernel(const float* __restrict__ sob)
{
    __shared__ float ks[3 * 125];
    const int tid = threadIdx.x;
    for (int i = tid; i < 375; i += 256) ks[i] = sob[i];
    __syncthreads();
    int v = blockIdx.x * 256 + tid;
    if (v >= M3) return;
    int x = v & 127, y = (v >> 7) & 127, z = v >> 14;
    float a0 = 0.f, a1 = 0.f, a2 = 0.f;
    for (int kz = 0; kz < 5; kz++) { int zz = z + kz - 2; if ((unsigned)zz >= 128u) continue;
    for (int ky = 0; ky < 5; ky++) { int yy = y + ky - 2; if ((unsigned)yy >= 128u) continue;
    for (int kx = 0; kx < 5; kx++) { int xx = x + kx - 2; if ((unsigned)xx >= 128u) continue;
        float val = g_vols[(zz * 128 + yy) * 128 + xx];
        int k = kz * 25 + ky * 5 + kx;
        a0 += val * ks[k];
        a1 += val * ks[125 + k];
        a2 += val * ks[250 + k];
    }}}
    g_vols[16 * M3 + v] = a0;
    g_vols[17 * M3 + v] = a1;
    g_vols[18 * M3 + v] = a2;
}

// ------------- per-sample: ray AABB, trilinear gather, MLP -------------------
__global__ void __launch_bounds__(128)
sample_kernel(const float* __restrict__ rays_o, const float* __restrict__ rays_d,
              const float* __restrict__ viewdirs,
              const float* __restrict__ w0, const float* __restrict__ b0,
              const float* __restrict__ w1, const float* __restrict__ b1,
              const float* __restrict__ w2, const float* __restrict__ b2,
              const float* __restrict__ w3, const float* __restrict__ b3,
              float* __restrict__ out)
{
    __shared__ float s_w0[58 * 64];
    __shared__ float s_w1[64 * 64];
    __shared__ float s_w2[64 * 64];
    __shared__ float s_w3[64 * 3];
    const int tid = threadIdx.x;
    for (int i = tid; i < 58 * 64; i += 128) s_w0[i] = w0[i];
    for (int i = tid; i < 64 * 64; i += 128) { s_w1[i] = w1[i]; s_w2[i] = w2[i]; }
    for (int i = tid; i < 192; i += 128) s_w3[i] = w3[i];
    __syncthreads();

    int idx = blockIdx.x * 128 + tid;
    if (idx >= BRAYS * NSAMP) return;
    int ray = idx / NSAMP;
    int s   = idx - ray * NSAMP;

    float ox = rays_o[ray * 3 + 0], oy = rays_o[ray * 3 + 1], oz = rays_o[ray * 3 + 2];
    float dx = rays_d[ray * 3 + 0], dy = rays_d[ray * 3 + 1], dz = rays_d[ray * 3 + 2];
    float vx = (dx == 0.f) ? 1e-6f : dx;
    float vy = (dy == 0.f) ? 1e-6f : dy;
    float vz = (dz == 0.f) ? 1e-6f : dz;
    float rax = (1.f - ox) / vx, rbx = (-1.f - ox) / vx;
    float ray_ = (1.f - oy) / vy, rby = (-1.f - oy) / vy;
    float raz = (1.f - oz) / vz, rbz = (-1.f - oz) / vz;
    float tmn = fmaxf(fmaxf(fminf(rax, rbx), fminf(ray_, rby)), fminf(raz, rbz));
    float tmx = fminf(fminf(fmaxf(rax, rbx), fmaxf(ray_, rby)), fmaxf(raz, rbz));
    float t_min = fminf(fmaxf(tmn, 0.05f), 2.5f);
    float t_max = fminf(fmaxf(tmx, 0.05f), 2.5f);
    bool mask = (t_max <= t_min);
    float dn = sqrtf(dx * dx + dy * dy + dz * dz);
    float interpx = t_min + STEPV * (float)s / dn;
    float px = ox + dx * interpx, py = oy + dy * interpx, pz = oz + dz * interpx;
    mask = mask || (px < -1.f) || (px > 1.f) || (py < -1.f) || (py > 1.f)
                || (pz < -1.f) || (pz > 1.f);
    if (mask) {
        g_sdfs[idx] = 100.f;
        g_rgbs[idx * 3 + 0] = 0.f;
        g_rgbs[idx * 3 + 1] = 0.f;
        g_rgbs[idx * 3 + 2] = 0.f;
        if (s == NSAMP - 1) out[BRAYS * 5 + ray] = 0.f;
        return;
    }
    float fx = fminf(fmaxf((px + 1.f) * 63.5f, 0.f), 127.f);
    float fy = fminf(fmaxf((py + 1.f) * 63.5f, 0.f), 127.f);
    float fz = fminf(fmaxf((pz + 1.f) * 63.5f, 0.f), 127.f);
    int i0x = (int)floorf(fx), i0y = (int)floorf(fy), i0z = (int)floorf(fz);
    int i1x = min(i0x + 1, 127), i1y = min(i0y + 1, 127), i1z = min(i0z + 1, 127);
    float twx = fx - (float)i0x, twy = fy - (float)i0y, twz = fz - (float)i0z;
    float wx0 = 1.f - twx, wy0 = 1.f - twy, wz0 = 1.f - twz;
    int o00 = (i0x * 128 + i0y) * 128;
    int o01 = (i0x * 128 + i1y) * 128;
    int o10 = (i1x * 128 + i0y) * 128;
    int o11 = (i1x * 128 + i1y) * 128;
    float w000 = wx0 * wy0 * wz0, w001 = wx0 * wy0 * twz;
    float w010 = wx0 * twy * wz0, w011 = wx0 * twy * twz;
    float w100 = twx * wy0 * wz0, w101 = twx * wy0 * twz;
    float w110 = twx * twy * wz0, w111 = twx * twy * twz;
    float samp[19];
#pragma unroll
    for (int c = 0; c < 19; c++) {
        const float* vc = g_vols + c * M3;
        samp[c] = w000 * __ldg(&vc[o00 + i0z]) + w001 * __ldg(&vc[o00 + i1z])
                + w010 * __ldg(&vc[o01 + i0z]) + w011 * __ldg(&vc[o01 + i1z])
                + w100 * __ldg(&vc[o10 + i0z]) + w101 * __ldg(&vc[o10 + i1z])
                + w110 * __ldg(&vc[o11 + i0z]) + w111 * __ldg(&vc[o11 + i1z]);
    }
    g_sdfs[idx] = samp[0];
    float gx = samp[16], gy = samp[17], gz = samp[18];
    float gn = sqrtf(gx * gx + gy * gy + gz * gz);
    float inv = 1.f / fmaxf(gn, 1e-12f);
    float nxx = gx * inv, nyy = gy * inv, nzz = gz * inv;
    float ux = viewdirs[ray * 3 + 0], uy = viewdirs[ray * 3 + 1], uz = viewdirs[ray * 3 + 2];
    float dot = -(ux * nxx + uy * nyy + uz * nzz);
    if (s == NSAMP - 1) out[BRAYS * 5 + ray] = -dot;
    float rx = 2.f * dot * nxx + ux;
    float ry = 2.f * dot * nyy + uy;
    float rz = 2.f * dot * nzz + uz;

    float h[58];
#pragma unroll
    for (int c = 0; c < 15; c++) h[c] = samp[1 + c];
    h[15] = dot;
    h[16] = rx; h[17] = ry; h[18] = rz;
    {
        int p = 19;
        float fr = 1.f;
#pragma unroll
        for (int e = 0; e < 6; e++) {
            float sx, cx, sy, cy, sz, cz;
            __sincosf(rx * fr, &sx, &cx);
            __sincosf(ry * fr, &sy, &cy);
            __sincosf(rz * fr, &sz, &cz);
            h[p + 0] = sx; h[p + 1] = sy; h[p + 2] = sz;
            h[p + 3] = cx; h[p + 4] = cy; h[p + 5] = cz;
            p += 6;
            fr *= 2.f;
        }
    }
    h[55] = px; h[56] = py; h[57] = pz;

    u64 acc2[32];
#pragma unroll
    for (int j = 0; j < 32; j++) {
        float2 bb = *(const float2*)(b0 + 2 * j);
        acc2[j] = pack2(bb.x, bb.y);
    }
#pragma unroll 1
    for (int i = 0; i < 58; i++) {
        u64 hv2 = pack2(h[i], h[i]);
        const u64* wp = (const u64*)(s_w0 + i * 64);
#pragma unroll
        for (int j = 0; j < 32; j++) fma2(acc2[j], hv2, wp[j]);
    }
    float act[64];
#pragma unroll
    for (int j = 0; j < 32; j++) {
        float2 p = unpack2(acc2[j]);
        act[2*j] = fmaxf(p.x, 0.f); act[2*j+1] = fmaxf(p.y, 0.f);
        float2 bb = *(const float2*)(b1 + 2 * j);
        acc2[j] = pack2(bb.x, bb.y);
    }
#pragma unroll 1
    for (int i = 0; i < 64; i++) {
        u64 hv2 = pack2(act[i], act[i]);
        const u64* wp = (const u64*)(s_w1 + i * 64);
#pragma unroll
        for (int j = 0; j < 32; j++) fma2(acc2[j], hv2, wp[j]);
    }
#pragma unroll
    for (int j = 0; j < 32; j++) {
        float2 p = unpack2(acc2[j]);
        act[2*j] = fmaxf(p.x, 0.f); act[2*j+1] = fmaxf(p.y, 0.f);
        float2 bb = *(const float2*)(b2 + 2 * j);
        acc2[j] = pack2(bb.x, bb.y);
    }
#pragma unroll 1
    for (int i = 0; i < 64; i++) {
        u64 hv2 = pack2(act[i], act[i]);
        const u64* wp = (const u64*)(s_w2 + i * 64);
#pragma unroll
        for (int j = 0; j < 32; j++) fma2(acc2[j], hv2, wp[j]);
    }
#pragma unroll
    for (int j = 0; j < 32; j++) {
        float2 p = unpack2(acc2[j]);
        act[2*j] = fmaxf(p.x, 0.f); act[2*j+1] = fmaxf(p.y, 0.f);
    }
    float r0 = __ldg(&b3[0]), r1 = __ldg(&b3[1]), r2 = __ldg(&b3[2]);
#pragma unroll 1
    for (int i = 0; i < 64; i++) {
        float hv = act[i];
        r0 += hv * s_w3[i * 3 + 0];
        r1 += hv * s_w3[i * 3 + 1];
        r2 += hv * s_w3[i * 3 + 2];
    }
    g_rgbs[idx * 3 + 0] = r0;
    g_rgbs[idx * 3 + 1] = r1;
    g_rgbs[idx * 3 + 2] = r2;
}

// ---------------- per-ray compositing: warp-per-ray with product scan --------
__global__ void __launch_bounds__(256)
render_kernel(const float* __restrict__ rays_o,
              const float* __restrict__ rays_d,
              const float* __restrict__ variance,
              float* __restrict__ out)
{
    int warp = (blockIdx.x * 256 + threadIdx.x) >> 5;
    int lane = threadIdx.x & 31;
    if (warp >= BRAYS) return;
    int ray = warp;
    float scale = expf(variance[0] * 10.f);
    float ox = rays_o[ray * 3 + 0], oy = rays_o[ray * 3 + 1], oz = rays_o[ray * 3 + 2];
    float dx = rays_d[ray * 3 + 0], dy = rays_d[ray * 3 + 1], dz = rays_d[ray * 3 + 2];
    float vx = (dx == 0.f) ? 1e-6f : dx;
    float vy = (dy == 0.f) ? 1e-6f : dy;
    float vz = (dz == 0.f) ? 1e-6f : dz;
    float rax = (1.f - ox) / vx, rbx = (-1.f - ox) / vx;
    float ray_ = (1.f - oy) / vy, rby = (-1.f - oy) / vy;
    float raz = (1.f - oz) / vz, rbz = (-1.f - oz) / vz;
    float tmn = fmaxf(fmaxf(fminf(rax, rbx), fminf(ray_, rby)), fminf(raz, rbz));
    float t_min = fminf(fmaxf(tmn, 0.05f), 2.5f);
    float dn = sqrtf(dx * dx + dy * dy + dz * dz);
    float base_dist = t_min * dn;

    const float* sd = g_sdfs + ray * NSAMP;
    float T = 1.f, rgb0 = 0.f, rgb1 = 0.f, rgb2 = 0.f, depth = 0.f;

    for (int base = 0; base < NSAMP - 1; base += 32) {
        int s = base + lane;
        bool v = s < NSAMP - 1;
        float alpha = 0.f;
        if (v) {
            float s0 = 1.f / (1.f + expf(-sd[s] * scale));
            float s1 = 1.f / (1.f + expf(-sd[s + 1] * scale));
            alpha = fmaxf((s0 - s1) / (s0 + 1e-10f), 0.f);
        }
        float om = 1.f - alpha;
        float p = om;
#pragma unroll
        for (int off = 1; off < 32; off <<= 1) {
            float t = __shfl_up_sync(0xffffffffu, p, off);
            if (lane >= off) p *= t;
        }
        float excl = __shfl_up_sync(0xffffffffu, p, 1);
        if (lane == 0) excl = 1.f;
        float wgt = T * excl * alpha;
        if (v) {
            out[BRAYS * 6 + ray * (NSAMP - 1) + s] = wgt;
            rgb0 += wgt * g_rgbs[(ray * NSAMP + s) * 3 + 0];
            rgb1 += wgt * g_rgbs[(ray * NSAMP + s) * 3 + 1];
            rgb2 += wgt * g_rgbs[(ray * NSAMP + s) * 3 + 2];
            depth += wgt * (base_dist + STEPV * (float)s);
        }
        T *= __shfl_sync(0xffffffffu, p, 31);
    }
#pragma unroll
    for (int off = 16; off; off >>= 1) {
        rgb0 += __shfl_xor_sync(0xffffffffu, rgb0, off);
        rgb1 += __shfl_xor_sync(0xffffffffu, rgb1, off);
        rgb2 += __shfl_xor_sync(0xffffffffu, rgb2, off);
        depth += __shfl_xor_sync(0xffffffffu, depth, off);
    }
    if (lane == 0) {
        out[ray * 3 + 0] = rgb0;
        out[ray * 3 + 1] = rgb1;
        out[ray * 3 + 2] = rgb2;
        out[BRAYS * 3 + ray] = depth;
        out[BRAYS * 4 + ray] = T;
    }
}

// -----------------------------------------------------------------------------
extern "C" void kernel_launch(void* const* d_in, const int* in_sizes, int n_in,
                              void* d_out, int out_size)
{
    const float* rays_o   = (const float*)d_in[0];
    const float* rays_d   = (const float*)d_in[1];
    const float* viewdirs = (const float*)d_in[2];
    const float* grid     = (const float*)d_in[3];
    const float* c1_w     = (const float*)d_in[4];
    const float* c1_b     = (const float*)d_in[5];
    const float* bn1_g    = (const float*)d_in[6];
    const float* bn1_beta = (const float*)d_in[7];
    const float* bn1_m    = (const float*)d_in[8];
    const float* bn1_v    = (const float*)d_in[9];
    const float* c2_w     = (const float*)d_in[10];
    const float* c2_b     = (const float*)d_in[11];
    const float* bn2_g    = (const float*)d_in[12];
    const float* bn2_beta = (const float*)d_in[13];
    const float* bn2_m    = (const float*)d_in[14];
    const float* bn2_v    = (const float*)d_in[15];
    const float* c3_w     = (const float*)d_in[16];
    const float* c3_b     = (const float*)d_in[17];
    const float* sobel    = (const float*)d_in[18];
    const float* variance = (const float*)d_in[19];
    const float* w0       = (const float*)d_in[20];
    const float* b0       = (const float*)d_in[21];
    const float* w1       = (const float*)d_in[22];
    const float* b1       = (const float*)d_in[23];
    const float* w2       = (const float*)d_in[24];
    const float* b2       = (const float*)d_in[25];
    const float* w3       = (const float*)d_in[26];
    const float* b3       = (const float*)d_in[27];
    float* out = (float*)d_out;

    cudaFuncSetAttribute(conv_tc_kernel<12, 2, 1>,
                         cudaFuncAttributeMaxDynamicSharedMemorySize, CONV_SMEM_H);
    cudaFuncSetAttribute(conv_tc_kernel<76, 10, 2>,
                         cudaFuncAttributeMaxDynamicSharedMemorySize, CONV_SMEM_H);

    // order: prep(1) conv1(2) conv2(3) deconv_tc(4=ncu slot) sobel sample render
    int prep_total = 12 * WCH_H + W3_TOTAL;
    prep_w_all<<<(prep_total + 255) / 256, 256>>>(c1_w, c2_w, c3_w);

    dim3 cgrid(8, 8, 8);
    conv_tc_kernel<12, 2, 1><<<cgrid, 512, CONV_SMEM_H>>>(
        grid, c1_b, bn1_g, bn1_beta, bn1_m, bn1_v);
    conv_tc_kernel<76, 10, 2><<<cgrid, 512, CONV_SMEM_H>>>(
        grid, c2_b, bn2_g, bn2_beta, bn2_m, bn2_v);
    deconv_tc_kernel<<<dim3(8, 8, 64), 256>>>(grid, c3_b);
    sobel_kernel<<<(M3 + 255) / 256, 256>>>(sobel);
    int total = BRAYS * NSAMP;
    sample_kernel<<<(total + 127) / 128, 128>>>(rays_o, rays_d, viewdirs,
                                                w0, b0, w1, b1, w2, b2, w3, b3, out);
    render_kernel<<<512, 256>>>(rays_o, rays_d, variance, out);
}